// round 6
// baseline (speedup 1.0000x reference)
#include <cuda_runtime.h>
#include <cuda_bf16.h>
#include <math.h>
#include <stdint.h>

#define NB   32
#define TT   128
#define BT   4096
#define CIN  4096
#define NF   64
#define GOUT 4096

// ---------------- scratch (device globals; no allocation allowed) ----------
__device__ float q_buf[(size_t)NB * TT * NF];
__device__ float k_buf[(size_t)NB * TT * NF];
__device__ __align__(1024) __nv_bfloat16 a_hi[(size_t)BT * CIN];     // x1 split
__device__ __align__(1024) __nv_bfloat16 a_lo[(size_t)BT * CIN];
__device__ __align__(1024) __nv_bfloat16 x2h[(size_t)BT * CIN];      // x2 split
__device__ __align__(1024) __nv_bfloat16 x2l[(size_t)BT * CIN];
__device__ __align__(1024) __nv_bfloat16 b_hi[(size_t)GOUT * CIN];   // wg split
__device__ __align__(1024) __nv_bfloat16 b_lo[(size_t)GOUT * CIN];
__device__ __align__(1024) __nv_bfloat16 w1h[(size_t)NF * CIN];
__device__ __align__(1024) __nv_bfloat16 w1l[(size_t)NF * CIN];
__device__ __align__(1024) __nv_bfloat16 w2h[(size_t)NF * CIN];
__device__ __align__(1024) __nv_bfloat16 w2l[(size_t)NF * CIN];
__device__ __align__(1024) __nv_bfloat16 g_h[(size_t)BT * GOUT];     // g split
__device__ __align__(1024) __nv_bfloat16 g_l[(size_t)BT * GOUT];
__device__ __align__(1024) __nv_bfloat16 act_h[(size_t)NB * TT * TT];
__device__ __align__(1024) __nv_bfloat16 act_l[(size_t)NB * TT * TT];

// ---------------- small PTX helpers ----------------------------------------
__device__ __forceinline__ uint32_t smem_u32(const void* p) {
    uint32_t a;
    asm("{ .reg .u64 t; cvta.to.shared.u64 t, %1; cvt.u32.u64 %0, t; }" : "=r"(a) : "l"(p));
    return a;
}
__device__ __forceinline__ void cp_async16(uint32_t dst, const void* src) {
    asm volatile("cp.async.cg.shared.global [%0], [%1], 16;" :: "r"(dst), "l"(src) : "memory");
}
__device__ __forceinline__ void ldm_x4(uint32_t& r0, uint32_t& r1, uint32_t& r2, uint32_t& r3,
                                       uint32_t addr) {
    asm volatile("ldmatrix.sync.aligned.m8n8.x4.shared.b16 {%0,%1,%2,%3}, [%4];"
                 : "=r"(r0), "=r"(r1), "=r"(r2), "=r"(r3) : "r"(addr));
}
__device__ __forceinline__ void ldm_x4_t(uint32_t& r0, uint32_t& r1, uint32_t& r2, uint32_t& r3,
                                         uint32_t addr) {
    asm volatile("ldmatrix.sync.aligned.m8n8.x4.trans.shared.b16 {%0,%1,%2,%3}, [%4];"
                 : "=r"(r0), "=r"(r1), "=r"(r2), "=r"(r3) : "r"(addr));
}
__device__ __forceinline__ void mma16816(float* c, const uint32_t* a, const uint32_t* b) {
    asm volatile("mma.sync.aligned.m16n8k16.row.col.f32.bf16.bf16.f32 "
                 "{%0,%1,%2,%3}, {%4,%5,%6,%7}, {%8,%9}, {%0,%1,%2,%3};"
                 : "+f"(c[0]), "+f"(c[1]), "+f"(c[2]), "+f"(c[3])
                 : "r"(a[0]), "r"(a[1]), "r"(a[2]), "r"(a[3]), "r"(b[0]), "r"(b[1]));
}
#define SWZ(o) ((o) ^ (((o) >> 3) & 0x70))

// ---------------- fp32 -> bf16 hi/lo split ----------------------------------
__global__ void __launch_bounds__(256)
split_bf16(const float* __restrict__ x, __nv_bfloat16* __restrict__ h,
           __nv_bfloat16* __restrict__ l, int n4)
{
    int i = blockIdx.x * blockDim.x + threadIdx.x;
    if (i >= n4) return;
    float4 v = ((const float4*)x)[i];
    __nv_bfloat16 h0 = __float2bfloat16(v.x);
    __nv_bfloat16 h1 = __float2bfloat16(v.y);
    __nv_bfloat16 h2 = __float2bfloat16(v.z);
    __nv_bfloat16 h3 = __float2bfloat16(v.w);
    __nv_bfloat16 l0 = __float2bfloat16(v.x - __bfloat162float(h0));
    __nv_bfloat16 l1 = __float2bfloat16(v.y - __bfloat162float(h1));
    __nv_bfloat16 l2 = __float2bfloat16(v.z - __bfloat162float(h2));
    __nv_bfloat16 l3 = __float2bfloat16(v.w - __bfloat162float(h3));
    ((__nv_bfloat162*)h)[2*i]   = __nv_bfloat162(h0, h1);
    ((__nv_bfloat162*)h)[2*i+1] = __nv_bfloat162(h2, h3);
    ((__nv_bfloat162*)l)[2*i]   = __nv_bfloat162(l0, l1);
    ((__nv_bfloat162*)l)[2*i+1] = __nv_bfloat162(l2, l3);
}

// ---------------- g GEMM: g = x1 @ wg^T + bg -> bf16 hi/lo -------------------
#define BKC 32
#define NCHUNK (CIN / BKC)
#define ST_AH 0
#define ST_AL 8192
#define ST_BH 16384
#define ST_BL 24576
#define STAGE_B 32768
#define SMEM_G (1024 + 2 * STAGE_B)

__global__ void __launch_bounds__(256, 2)
g_gemm_mma(const __nv_bfloat16* __restrict__ Ah, const __nv_bfloat16* __restrict__ Al,
           const __nv_bfloat16* __restrict__ Bh, const __nv_bfloat16* __restrict__ Bl,
           const float* __restrict__ bias,
           __nv_bfloat16* __restrict__ Gh, __nv_bfloat16* __restrict__ Gl)
{
    extern __shared__ char smem_raw[];
    const uint32_t base = (smem_u32(smem_raw) + 1023u) & ~1023u;

    const int tid  = threadIdx.x;
    const int wid  = tid >> 5;
    const int lane = tid & 31;
    const int bm = blockIdx.y * 128;
    const int bn = blockIdx.x * 128;
    const int wm = (wid >> 2) * 64;
    const int wn = (wid & 3) * 32;

    auto load_chunk = [&](int c, uint32_t st) {
        const int k0 = c * BKC;
        #pragma unroll
        for (int i = 0; i < 2; i++) {
            int u   = tid + i * 256;
            int row = u >> 2;
            int cu  = u & 3;
            uint32_t so = SWZ((uint32_t)(row * 64 + cu * 16));
            size_t ga = (size_t)(bm + row) * CIN + k0 + cu * 8;
            size_t gb = (size_t)(bn + row) * CIN + k0 + cu * 8;
            cp_async16(st + ST_AH + so, Ah + ga);
            cp_async16(st + ST_AL + so, Al + ga);
            cp_async16(st + ST_BH + so, Bh + gb);
            cp_async16(st + ST_BL + so, Bl + gb);
        }
        asm volatile("cp.async.commit_group;" ::: "memory");
    };

    load_chunk(0, base);
    load_chunk(1, base + STAGE_B);

    float acc[4][4][4];
    #pragma unroll
    for (int i = 0; i < 4; i++)
        #pragma unroll
        for (int j = 0; j < 4; j++)
            #pragma unroll
            for (int r = 0; r < 4; r++) acc[i][j][r] = 0.f;

    const int sub = lane >> 3;
    const int lr  = lane & 7;
    const int a_row_off = (sub & 1) * 8 + lr;
    const int a_cu_off  = (sub >> 1);
    const int b_row_off = (sub >> 1) * 8 + lr;
    const int b_cu_off  = (sub & 1);

    for (int c = 0; c < NCHUNK; c++) {
        const uint32_t st = base + (uint32_t)(c & 1) * STAGE_B;
        if (c < NCHUNK - 1) asm volatile("cp.async.wait_group 1;" ::: "memory");
        else                asm volatile("cp.async.wait_group 0;" ::: "memory");
        __syncthreads();

        #pragma unroll
        for (int ks = 0; ks < 2; ks++) {
            uint32_t aH[4][4], aL[4][4];
            #pragma unroll
            for (int mt = 0; mt < 4; mt++) {
                uint32_t off = SWZ((uint32_t)((wm + mt*16 + a_row_off) * 64
                                              + (ks*2 + a_cu_off) * 16));
                ldm_x4(aH[mt][0], aH[mt][1], aH[mt][2], aH[mt][3], st + ST_AH + off);
                ldm_x4(aL[mt][0], aL[mt][1], aL[mt][2], aL[mt][3], st + ST_AL + off);
            }
            #pragma unroll
            for (int np = 0; np < 2; np++) {
                uint32_t bH[2][2], bL[2][2];
                uint32_t off = SWZ((uint32_t)((wn + np*16 + b_row_off) * 64
                                              + (ks*2 + b_cu_off) * 16));
                ldm_x4(bH[0][0], bH[0][1], bH[1][0], bH[1][1], st + ST_BH + off);
                ldm_x4(bL[0][0], bL[0][1], bL[1][0], bL[1][1], st + ST_BL + off);
                // term-major: consecutive mmas hit different accumulators
                #pragma unroll
                for (int mt = 0; mt < 4; mt++)
                    #pragma unroll
                    for (int nh = 0; nh < 2; nh++)
                        mma16816(acc[mt][np*2 + nh], aH[mt], bH[nh]);
                #pragma unroll
                for (int mt = 0; mt < 4; mt++)
                    #pragma unroll
                    for (int nh = 0; nh < 2; nh++)
                        mma16816(acc[mt][np*2 + nh], aH[mt], bL[nh]);
                #pragma unroll
                for (int mt = 0; mt < 4; mt++)
                    #pragma unroll
                    for (int nh = 0; nh < 2; nh++)
                        mma16816(acc[mt][np*2 + nh], aL[mt], bH[nh]);
            }
        }
        __syncthreads();
        if (c + 2 < NCHUNK) load_chunk(c + 2, st);
    }

    const int q = lane >> 2;
    const int i2 = (lane & 3) * 2;
    #pragma unroll
    for (int mt = 0; mt < 4; mt++) {
        #pragma unroll
        for (int nt = 0; nt < 4; nt++) {
            int m0 = bm + wm + mt*16 + q;
            int n0 = bn + wn + nt*8 + i2;
            float2 bv = *(const float2*)(bias + n0);
            float v00 = acc[mt][nt][0] + bv.x, v01 = acc[mt][nt][1] + bv.y;
            float v10 = acc[mt][nt][2] + bv.x, v11 = acc[mt][nt][3] + bv.y;
            __nv_bfloat16 h00 = __float2bfloat16(v00), h01 = __float2bfloat16(v01);
            __nv_bfloat16 h10 = __float2bfloat16(v10), h11 = __float2bfloat16(v11);
            __nv_bfloat16 l00 = __float2bfloat16(v00 - __bfloat162float(h00));
            __nv_bfloat16 l01 = __float2bfloat16(v01 - __bfloat162float(h01));
            __nv_bfloat16 l10 = __float2bfloat16(v10 - __bfloat162float(h10));
            __nv_bfloat16 l11 = __float2bfloat16(v11 - __bfloat162float(h11));
            *(__nv_bfloat162*)(Gh + (size_t)m0 * GOUT + n0)     = __nv_bfloat162(h00, h01);
            *(__nv_bfloat162*)(Gh + (size_t)(m0+8) * GOUT + n0) = __nv_bfloat162(h10, h11);
            *(__nv_bfloat162*)(Gl + (size_t)m0 * GOUT + n0)     = __nv_bfloat162(l00, l01);
            *(__nv_bfloat162*)(Gl + (size_t)(m0+8) * GOUT + n0) = __nv_bfloat162(l10, l11);
        }
    }
}

// ---------------- q/k GEMM: 64x64 tile, split-bf16 mma -----------------------
#define QK_BK 64
#define QK_NCH (CIN / QK_BK)
#define QK_AH 0
#define QK_AL 8192
#define QK_BH 16384
#define QK_BL 24576
#define QK_STAGE 32768
#define SMEM_QK (1024 + 2 * QK_STAGE)

__global__ void __launch_bounds__(128, 1)
qk_gemm_mma(const __nv_bfloat16* __restrict__ X1h, const __nv_bfloat16* __restrict__ X1l,
            const __nv_bfloat16* __restrict__ X2h, const __nv_bfloat16* __restrict__ X2l,
            const __nv_bfloat16* __restrict__ W1h, const __nv_bfloat16* __restrict__ W1l,
            const __nv_bfloat16* __restrict__ W2h, const __nv_bfloat16* __restrict__ W2l,
            const float* __restrict__ b1, const float* __restrict__ b2,
            float* __restrict__ Q, float* __restrict__ K)
{
    extern __shared__ char smem_raw[];
    const uint32_t base = (smem_u32(smem_raw) + 1023u) & ~1023u;

    const int sel = blockIdx.y;
    const __nv_bfloat16* Ah = sel ? X2h : X1h;
    const __nv_bfloat16* Al = sel ? X2l : X1l;
    const __nv_bfloat16* Bh = sel ? W2h : W1h;
    const __nv_bfloat16* Bl = sel ? W2l : W1l;
    const float* bias = sel ? b2 : b1;
    float* C = sel ? K : Q;

    const int tid  = threadIdx.x;
    const int wid  = tid >> 5;
    const int lane = tid & 31;
    const int bm = blockIdx.x * 64;
    const int wm = (wid >> 1) * 32;
    const int wn = (wid & 1) * 32;

    auto load_chunk = [&](int c, uint32_t st) {
        const int k0 = c * QK_BK;
        #pragma unroll
        for (int i = 0; i < 4; i++) {
            int u   = tid + i * 128;
            int row = u >> 3;
            int ku  = u & 7;
            uint32_t so = SWZ((uint32_t)(row * 128 + ku * 16));
            size_t ga = (size_t)(bm + row) * CIN + k0 + ku * 8;
            size_t gb = (size_t)row * CIN + k0 + ku * 8;
            cp_async16(st + QK_AH + so, Ah + ga);
            cp_async16(st + QK_AL + so, Al + ga);
            cp_async16(st + QK_BH + so, Bh + gb);
            cp_async16(st + QK_BL + so, Bl + gb);
        }
        asm volatile("cp.async.commit_group;" ::: "memory");
    };

    load_chunk(0, base);
    load_chunk(1, base + QK_STAGE);

    float acc[2][4][4];
    #pragma unroll
    for (int i = 0; i < 2; i++)
        #pragma unroll
        for (int j = 0; j < 4; j++)
            #pragma unroll
            for (int r = 0; r < 4; r++) acc[i][j][r] = 0.f;

    const int sub = lane >> 3;
    const int lr  = lane & 7;
    const int a_row_off = (sub & 1) * 8 + lr;
    const int a_cu_off  = (sub >> 1);
    const int b_row_off = (sub >> 1) * 8 + lr;
    const int b_cu_off  = (sub & 1);

    for (int c = 0; c < QK_NCH; c++) {
        const uint32_t st = base + (uint32_t)(c & 1) * QK_STAGE;
        if (c < QK_NCH - 1) asm volatile("cp.async.wait_group 1;" ::: "memory");
        else                asm volatile("cp.async.wait_group 0;" ::: "memory");
        __syncthreads();

        #pragma unroll
        for (int ks = 0; ks < 4; ks++) {
            uint32_t aH[2][4], aL[2][4], bH[4][2], bL[4][2];
            #pragma unroll
            for (int mt = 0; mt < 2; mt++) {
                uint32_t off = SWZ((uint32_t)((wm + mt*16 + a_row_off) * 128
                                              + (ks*2 + a_cu_off) * 16));
                ldm_x4(aH[mt][0], aH[mt][1], aH[mt][2], aH[mt][3], st + QK_AH + off);
                ldm_x4(aL[mt][0], aL[mt][1], aL[mt][2], aL[mt][3], st + QK_AL + off);
            }
            #pragma unroll
            for (int np = 0; np < 2; np++) {
                uint32_t off = SWZ((uint32_t)((wn + np*16 + b_row_off) * 128
                                              + (ks*2 + b_cu_off) * 16));
                ldm_x4(bH[2*np][0], bH[2*np][1], bH[2*np+1][0], bH[2*np+1][1],
                       st + QK_BH + off);
                ldm_x4(bL[2*np][0], bL[2*np][1], bL[2*np+1][0], bL[2*np+1][1],
                       st + QK_BL + off);
            }
            // term-major ordering
            #pragma unroll
            for (int mt = 0; mt < 2; mt++)
                #pragma unroll
                for (int nt = 0; nt < 4; nt++)
                    mma16816(acc[mt][nt], aH[mt], bH[nt]);
            #pragma unroll
            for (int mt = 0; mt < 2; mt++)
                #pragma unroll
                for (int nt = 0; nt < 4; nt++)
                    mma16816(acc[mt][nt], aH[mt], bL[nt]);
            #pragma unroll
            for (int mt = 0; mt < 2; mt++)
                #pragma unroll
                for (int nt = 0; nt < 4; nt++)
                    mma16816(acc[mt][nt], aL[mt], bH[nt]);
        }
        __syncthreads();
        if (c + 2 < QK_NCH) load_chunk(c + 2, st);
    }

    const int q = lane >> 2;
    const int i2 = (lane & 3) * 2;
    #pragma unroll
    for (int mt = 0; mt < 2; mt++) {
        #pragma unroll
        for (int nt = 0; nt < 4; nt++) {
            int m0 = bm + wm + mt*16 + q;
            int n0 = wn + nt*8 + i2;
            float2 bv = *(const float2*)(bias + n0);
            float2 o0 = { acc[mt][nt][0] + bv.x, acc[mt][nt][1] + bv.y };
            float2 o1 = { acc[mt][nt][2] + bv.x, acc[mt][nt][3] + bv.y };
            *(float2*)(C + (size_t)m0 * NF + n0)     = o0;
            *(float2*)(C + (size_t)(m0+8) * NF + n0) = o1;
        }
    }
}

// ---------------- scores + fused activation -> act hi/lo ---------------------
__global__ void __launch_bounds__(512)
scores_act_kernel(const float* __restrict__ actw,
                  const float* __restrict__ qb,
                  const float* __restrict__ kb,
                  __nv_bfloat16* __restrict__ ah,
                  __nv_bfloat16* __restrict__ al)
{
    const int b  = blockIdx.x;
    const int s  = blockIdx.y * 32 + (threadIdx.x >> 4);
    const int tp = threadIdx.x & 15;

    __shared__ float qs[TT * NF];
    for (int idx = threadIdx.x; idx < TT*NF; idx += 512)
        qs[idx] = qb[(size_t)b*TT*NF + idx];

    float kr[NF];
    #pragma unroll
    for (int f = 0; f < NF; ++f) kr[f] = kb[((size_t)b*TT + s)*NF + f];
    __syncthreads();

    float col[8];
    float mx = -1e30f;
    #pragma unroll
    for (int i = 0; i < 8; ++i) {
        const float* qrow = qs + (tp*8 + i)*NF;
        float v = 0.f;
        #pragma unroll
        for (int f = 0; f < NF; ++f) v = fmaf(qrow[f], kr[f], v);
        col[i] = v;
        mx = fmaxf(mx, v);
    }
    #pragma unroll
    for (int d = 1; d < 16; d <<= 1)
        mx = fmaxf(mx, __shfl_xor_sync(0xffffffffu, mx, d));
    float sum = 0.f;
    #pragma unroll
    for (int i = 0; i < 8; ++i) sum += expf(col[i] - mx);
    #pragma unroll
    for (int d = 1; d < 16; d <<= 1)
        sum += __shfl_xor_sync(0xffffffffu, sum, d);
    const float inv = 1.f / sum;
    const float w0 = actw[0], w1 = actw[1], w2 = actw[2];
    __nv_bfloat16* ph = ah + (size_t)b*TT*TT + s;
    __nv_bfloat16* pl = al + (size_t)b*TT*TT + s;
    #pragma unroll
    for (int i = 0; i < 8; ++i) {
        int t = tp*8 + i;
        float v = col[i];
        float a = w0 * fmaxf(v, 0.f)
                + w1 * (1.f / (1.f + expf(-v)))
                + w2 * (expf(v - mx) * inv);
        __nv_bfloat16 h = __float2bfloat16(a);
        __nv_bfloat16 l = __float2bfloat16(a - __bfloat162float(h));
        ph[t*TT] = h;
        pl[t*TT] = l;
    }
}

// ---------------- out GEMM: out[b] = act[b] @ g[b]  (K=128) -------------------
#define OROW 272
#define O_AH 0
#define O_AL (128 * OROW)
#define O_BH (2 * 128 * OROW)
#define O_BL (3 * 128 * OROW)
#define SMEM_OUT (4 * 128 * OROW + 1024)

__global__ void __launch_bounds__(256, 1)
out_gemm_mma(const __nv_bfloat16* __restrict__ AHg, const __nv_bfloat16* __restrict__ ALg,
             const __nv_bfloat16* __restrict__ GH, const __nv_bfloat16* __restrict__ GL,
             float* __restrict__ Out)
{
    extern __shared__ char smem_raw[];
    const uint32_t base = (smem_u32(smem_raw) + 1023u) & ~1023u;

    const int tid  = threadIdx.x;
    const int wid  = tid >> 5;
    const int lane = tid & 31;
    const int b  = blockIdx.y;
    const int bn = blockIdx.x * 128;
    const int wm = (wid >> 2) * 64;
    const int wn = (wid & 3) * 32;

    #pragma unroll
    for (int i = 0; i < 8; i++) {
        int u   = tid + i * 256;
        int row = u >> 4;
        int cu  = u & 15;
        uint32_t so = (uint32_t)(row * OROW + cu * 16);
        size_t ga = ((size_t)b*TT + row) * TT + cu * 8;
        size_t gb = ((size_t)b*TT + row) * GOUT + bn + cu * 8;
        cp_async16(base + O_AH + so, AHg + ga);
        cp_async16(base + O_AL + so, ALg + ga);
        cp_async16(base + O_BH + so, GH + gb);
        cp_async16(base + O_BL + so, GL + gb);
    }
    asm volatile("cp.async.commit_group;" ::: "memory");
    asm volatile("cp.async.wait_group 0;" ::: "memory");
    __syncthreads();

    float acc[4][4][4];
    #pragma unroll
    for (int i = 0; i < 4; i++)
        #pragma unroll
        for (int j = 0; j < 4; j++)
            #pragma unroll
            for (int r = 0; r < 4; r++) acc[i][j][r] = 0.f;

    const int sub = lane >> 3;
    const int lr  = lane & 7;
    const int a_row_off = (sub & 1) * 8 + lr;
    const int a_cu_off  = (sub >> 1);
    const int bt_row_off = (sub & 1) * 8 + lr;
    const int bt_cu_off  = (sub >> 1);

    #pragma unroll
    for (int ks = 0; ks < 8; ks++) {
        uint32_t aH[4][4], aL[4][4], bH[4][2], bL[4][2];
        #pragma unroll
        for (int mt = 0; mt < 4; mt++) {
            uint32_t off = (uint32_t)((wm + mt*16 + a_row_off) * OROW
                                      + ks*32 + a_cu_off * 16);
            ldm_x4(aH[mt][0], aH[mt][1], aH[mt][2], aH[mt][3], base + O_AH + off);
            ldm_x4(aL[mt][0], aL[mt][1], aL[mt][2], aL[mt][3], base + O_AL + off);
        }
        #pragma unroll
        for (int np = 0; np < 2; np++) {
            int n0 = wn + np*16;
            uint32_t off = (uint32_t)((ks*16 + bt_row_off) * OROW
                                      + n0*2 + bt_cu_off * 16);
            ldm_x4_t(bH[2*np][0], bH[2*np][1], bH[2*np+1][0], bH[2*np+1][1],
                     base + O_BH + off);
            ldm_x4_t(bL[2*np][0], bL[2*np][1], bL[2*np+1][0], bL[2*np+1][1],
                     base + O_BL + off);
        }
        // term-major ordering
        #pragma unroll
        for (int mt = 0; mt < 4; mt++)
            #pragma unroll
            for (int nt = 0; nt < 4; nt++)
                mma16816(acc[mt][nt], aH[mt], bH[nt]);
        #pragma unroll
        for (int mt = 0; mt < 4; mt++)
            #pragma unroll
            for (int nt = 0; nt < 4; nt++)
                mma16816(acc[mt][nt], aH[mt], bL[nt]);
        #pragma unroll
        for (int mt = 0; mt < 4; mt++)
            #pragma unroll
            for (int nt = 0; nt < 4; nt++)
                mma16816(acc[mt][nt], aL[mt], bH[nt]);
    }

    const int q = lane >> 2;
    const int i2 = (lane & 3) * 2;
    #pragma unroll
    for (int mt = 0; mt < 4; mt++) {
        #pragma unroll
        for (int nt = 0; nt < 4; nt++) {
            int m0 = wm + mt*16 + q;
            int n0 = bn + wn + nt*8 + i2;
            float2 o0 = { acc[mt][nt][0], acc[mt][nt][1] };
            float2 o1 = { acc[mt][nt][2], acc[mt][nt][3] };
            *(float2*)(Out + ((size_t)b*TT + m0) * GOUT + n0)     = o0;
            *(float2*)(Out + ((size_t)b*TT + m0 + 8) * GOUT + n0) = o1;
        }
    }
}

// ---------------------------------------------------------------------------
extern "C" void kernel_launch(void* const* d_in, const int* in_sizes, int n_in,
                              void* d_out, int out_size)
{
    const float* x1   = (const float*)d_in[0];
    const float* x2   = (const float*)d_in[1];
    const float* actw = (const float*)d_in[2];
    const float* w1   = (const float*)d_in[3];
    const float* b1   = (const float*)d_in[4];
    const float* w2   = (const float*)d_in[5];
    const float* b2   = (const float*)d_in[6];
    const float* wg   = (const float*)d_in[7];
    const float* bg   = (const float*)d_in[8];
    float* out = (float*)d_out;

    float *qp, *kp;
    __nv_bfloat16 *ahp, *alp, *x2hp, *x2lp, *bhp, *blp;
    __nv_bfloat16 *w1hp, *w1lp, *w2hp, *w2lp, *ghp, *glp, *acthp, *actlp;
    cudaGetSymbolAddress((void**)&qp, q_buf);
    cudaGetSymbolAddress((void**)&kp, k_buf);
    cudaGetSymbolAddress((void**)&ahp, a_hi);
    cudaGetSymbolAddress((void**)&alp, a_lo);
    cudaGetSymbolAddress((void**)&x2hp, x2h);
    cudaGetSymbolAddress((void**)&x2lp, x2l);
    cudaGetSymbolAddress((void**)&bhp, b_hi);
    cudaGetSymbolAddress((void**)&blp, b_lo);
    cudaGetSymbolAddress((void**)&w1hp, w1h);
    cudaGetSymbolAddress((void**)&w1lp, w1l);
    cudaGetSymbolAddress((void**)&w2hp, w2h);
    cudaGetSymbolAddress((void**)&w2lp, w2l);
    cudaGetSymbolAddress((void**)&ghp, g_h);
    cudaGetSymbolAddress((void**)&glp, g_l);
    cudaGetSymbolAddress((void**)&acthp, act_h);
    cudaGetSymbolAddress((void**)&actlp, act_l);

    cudaFuncSetAttribute(g_gemm_mma, cudaFuncAttributeMaxDynamicSharedMemorySize, SMEM_G);
    cudaFuncSetAttribute(qk_gemm_mma, cudaFuncAttributeMaxDynamicSharedMemorySize, SMEM_QK);
    cudaFuncSetAttribute(out_gemm_mma, cudaFuncAttributeMaxDynamicSharedMemorySize, SMEM_OUT);

    // splits
    {
        int n4 = (BT * CIN) / 4;
        split_bf16<<<(n4 + 255) / 256, 256>>>(x1, ahp, alp, n4);
        split_bf16<<<(n4 + 255) / 256, 256>>>(x2, x2hp, x2lp, n4);
        split_bf16<<<(n4 + 255) / 256, 256>>>(wg, bhp, blp, n4);
        int w4 = (NF * CIN) / 4;
        split_bf16<<<(w4 + 255) / 256, 256>>>(w1, w1hp, w1lp, w4);
        split_bf16<<<(w4 + 255) / 256, 256>>>(w2, w2hp, w2lp, w4);
    }

    // q and k projections
    qk_gemm_mma<<<dim3(BT/64, 2), 128, SMEM_QK>>>(ahp, alp, x2hp, x2lp,
                                                  w1hp, w1lp, w2hp, w2lp,
                                                  b1, b2, qp, kp);

    // g = x1 @ wg^T + bg -> bf16 hi/lo
    g_gemm_mma<<<dim3(GOUT/128, BT/128), 256, SMEM_G>>>(ahp, alp, bhp, blp, bg, ghp, glp);

    // scores -> fused activation -> act hi/lo
    scores_act_kernel<<<dim3(NB, 4), 512>>>(actw, qp, kp, acthp, actlp);

    // out[b] = act[b] @ g[b]
    out_gemm_mma<<<dim3(GOUT/128, NB), 256, SMEM_OUT>>>(acthp, actlp, ghp, glp, out);
}

// round 7
// speedup vs baseline: 1.2883x; 1.2883x over previous
#include <cuda_runtime.h>
#include <cuda_bf16.h>
#include <cuda_fp16.h>
#include <math.h>
#include <stdint.h>

#define NB   32
#define TT   128
#define BT   4096
#define CIN  4096
#define NF   64
#define GOUT 4096

// ---------------- scratch (device globals; no allocation allowed) ----------
__device__ float q_buf[(size_t)NB * TT * NF];
__device__ float k_buf[(size_t)NB * TT * NF];
__device__ __align__(1024) __nv_bfloat16 a_hi[(size_t)BT * CIN];     // x1 bf16 split (qk)
__device__ __align__(1024) __nv_bfloat16 a_lo[(size_t)BT * CIN];
__device__ __align__(1024) __nv_bfloat16 x2h[(size_t)BT * CIN];      // x2 bf16 split (qk)
__device__ __align__(1024) __nv_bfloat16 x2l[(size_t)BT * CIN];
__device__ __align__(1024) __half       x1f[(size_t)BT * CIN];       // x1 fp16 (g A)
__device__ __align__(1024) __half       wgh[(size_t)GOUT * CIN];     // wg fp16 split (g B)
__device__ __align__(1024) __half       wgl[(size_t)GOUT * CIN];
__device__ __align__(1024) __nv_bfloat16 w1h[(size_t)NF * CIN];
__device__ __align__(1024) __nv_bfloat16 w1l[(size_t)NF * CIN];
__device__ __align__(1024) __nv_bfloat16 w2h[(size_t)NF * CIN];
__device__ __align__(1024) __nv_bfloat16 w2l[(size_t)NF * CIN];
__device__ __align__(1024) __nv_bfloat16 g_h[(size_t)BT * GOUT];     // g bf16 split
__device__ __align__(1024) __nv_bfloat16 g_l[(size_t)BT * GOUT];
__device__ __align__(1024) __nv_bfloat16 act_h[(size_t)NB * TT * TT];
__device__ __align__(1024) __nv_bfloat16 act_l[(size_t)NB * TT * TT];

// ---------------- small PTX helpers ----------------------------------------
__device__ __forceinline__ uint32_t smem_u32(const void* p) {
    uint32_t a;
    asm("{ .reg .u64 t; cvta.to.shared.u64 t, %1; cvt.u32.u64 %0, t; }" : "=r"(a) : "l"(p));
    return a;
}
__device__ __forceinline__ void cp_async16(uint32_t dst, const void* src) {
    asm volatile("cp.async.cg.shared.global [%0], [%1], 16;" :: "r"(dst), "l"(src) : "memory");
}
__device__ __forceinline__ void ldm_x4(uint32_t& r0, uint32_t& r1, uint32_t& r2, uint32_t& r3,
                                       uint32_t addr) {
    asm volatile("ldmatrix.sync.aligned.m8n8.x4.shared.b16 {%0,%1,%2,%3}, [%4];"
                 : "=r"(r0), "=r"(r1), "=r"(r2), "=r"(r3) : "r"(addr));
}
__device__ __forceinline__ void ldm_x4_t(uint32_t& r0, uint32_t& r1, uint32_t& r2, uint32_t& r3,
                                         uint32_t addr) {
    asm volatile("ldmatrix.sync.aligned.m8n8.x4.trans.shared.b16 {%0,%1,%2,%3}, [%4];"
                 : "=r"(r0), "=r"(r1), "=r"(r2), "=r"(r3) : "r"(addr));
}
__device__ __forceinline__ void mma16816(float* c, const uint32_t* a, const uint32_t* b) {
    asm volatile("mma.sync.aligned.m16n8k16.row.col.f32.bf16.bf16.f32 "
                 "{%0,%1,%2,%3}, {%4,%5,%6,%7}, {%8,%9}, {%0,%1,%2,%3};"
                 : "+f"(c[0]), "+f"(c[1]), "+f"(c[2]), "+f"(c[3])
                 : "r"(a[0]), "r"(a[1]), "r"(a[2]), "r"(a[3]), "r"(b[0]), "r"(b[1]));
}
__device__ __forceinline__ void mma16816h(float* c, const uint32_t* a, const uint32_t* b) {
    asm volatile("mma.sync.aligned.m16n8k16.row.col.f32.f16.f16.f32 "
                 "{%0,%1,%2,%3}, {%4,%5,%6,%7}, {%8,%9}, {%0,%1,%2,%3};"
                 : "+f"(c[0]), "+f"(c[1]), "+f"(c[2]), "+f"(c[3])
                 : "r"(a[0]), "r"(a[1]), "r"(a[2]), "r"(a[3]), "r"(b[0]), "r"(b[1]));
}
#define SWZ(o) ((o) ^ (((o) >> 3) & 0x70))

// ---------------- conversion kernels -----------------------------------------
__global__ void __launch_bounds__(256)
split_bf16(const float* __restrict__ x, __nv_bfloat16* __restrict__ h,
           __nv_bfloat16* __restrict__ l, int n4)
{
    int i = blockIdx.x * blockDim.x + threadIdx.x;
    if (i >= n4) return;
    float4 v = ((const float4*)x)[i];
    __nv_bfloat16 h0 = __float2bfloat16(v.x);
    __nv_bfloat16 h1 = __float2bfloat16(v.y);
    __nv_bfloat16 h2 = __float2bfloat16(v.z);
    __nv_bfloat16 h3 = __float2bfloat16(v.w);
    __nv_bfloat16 l0 = __float2bfloat16(v.x - __bfloat162float(h0));
    __nv_bfloat16 l1 = __float2bfloat16(v.y - __bfloat162float(h1));
    __nv_bfloat16 l2 = __float2bfloat16(v.z - __bfloat162float(h2));
    __nv_bfloat16 l3 = __float2bfloat16(v.w - __bfloat162float(h3));
    ((__nv_bfloat162*)h)[2*i]   = __nv_bfloat162(h0, h1);
    ((__nv_bfloat162*)h)[2*i+1] = __nv_bfloat162(h2, h3);
    ((__nv_bfloat162*)l)[2*i]   = __nv_bfloat162(l0, l1);
    ((__nv_bfloat162*)l)[2*i+1] = __nv_bfloat162(l2, l3);
}

__global__ void __launch_bounds__(256)
split_f16(const float* __restrict__ x, __half* __restrict__ h,
          __half* __restrict__ l, int n4)
{
    int i = blockIdx.x * blockDim.x + threadIdx.x;
    if (i >= n4) return;
    float4 v = ((const float4*)x)[i];
    __half h0 = __float2half_rn(v.x);
    __half h1 = __float2half_rn(v.y);
    __half h2 = __float2half_rn(v.z);
    __half h3 = __float2half_rn(v.w);
    __half l0 = __float2half_rn(v.x - __half2float(h0));
    __half l1 = __float2half_rn(v.y - __half2float(h1));
    __half l2 = __float2half_rn(v.z - __half2float(h2));
    __half l3 = __float2half_rn(v.w - __half2float(h3));
    ((__half2*)h)[2*i]   = __half2(h0, h1);
    ((__half2*)h)[2*i+1] = __half2(h2, h3);
    ((__half2*)l)[2*i]   = __half2(l0, l1);
    ((__half2*)l)[2*i+1] = __half2(l2, l3);
}

__global__ void __launch_bounds__(256)
conv_f16(const float* __restrict__ x, __half* __restrict__ h, int n4)
{
    int i = blockIdx.x * blockDim.x + threadIdx.x;
    if (i >= n4) return;
    float4 v = ((const float4*)x)[i];
    ((__half2*)h)[2*i]   = __half2(__float2half_rn(v.x), __float2half_rn(v.y));
    ((__half2*)h)[2*i+1] = __half2(__float2half_rn(v.z), __float2half_rn(v.w));
}

// ---------------- g GEMM: g = fp16(x1) @ (wgh+wgl)^T + bg -> bf16 hi/lo ------
// 2-term fp16 split: C = A*Bh + A*Bl. Tile 128x128, BK=32, 8 warps.
#define BKC 32
#define NCHUNK (CIN / BKC)
#define ST_A  0
#define ST_BH 8192
#define ST_BL 16384
#define STAGE_B 24576
#define SMEM_G (1024 + 2 * STAGE_B)

__global__ void __launch_bounds__(256, 2)
g_gemm_mma(const __half* __restrict__ A,
           const __half* __restrict__ Bh, const __half* __restrict__ Bl,
           const float* __restrict__ bias,
           __nv_bfloat16* __restrict__ Gh, __nv_bfloat16* __restrict__ Gl)
{
    extern __shared__ char smem_raw[];
    const uint32_t base = (smem_u32(smem_raw) + 1023u) & ~1023u;

    const int tid  = threadIdx.x;
    const int wid  = tid >> 5;
    const int lane = tid & 31;
    const int bm = blockIdx.y * 128;
    const int bn = blockIdx.x * 128;
    const int wm = (wid >> 2) * 64;
    const int wn = (wid & 3) * 32;

    auto load_chunk = [&](int c, uint32_t st) {
        const int k0 = c * BKC;
        #pragma unroll
        for (int i = 0; i < 2; i++) {
            int u   = tid + i * 256;
            int row = u >> 2;
            int cu  = u & 3;
            uint32_t so = SWZ((uint32_t)(row * 64 + cu * 16));
            size_t ga = (size_t)(bm + row) * CIN + k0 + cu * 8;
            size_t gb = (size_t)(bn + row) * CIN + k0 + cu * 8;
            cp_async16(st + ST_A  + so, A  + ga);
            cp_async16(st + ST_BH + so, Bh + gb);
            cp_async16(st + ST_BL + so, Bl + gb);
        }
        asm volatile("cp.async.commit_group;" ::: "memory");
    };

    load_chunk(0, base);
    load_chunk(1, base + STAGE_B);

    float acc[4][4][4];
    #pragma unroll
    for (int i = 0; i < 4; i++)
        #pragma unroll
        for (int j = 0; j < 4; j++)
            #pragma unroll
            for (int r = 0; r < 4; r++) acc[i][j][r] = 0.f;

    const int sub = lane >> 3;
    const int lr  = lane & 7;
    const int a_row_off = (sub & 1) * 8 + lr;
    const int a_cu_off  = (sub >> 1);
    const int b_row_off = (sub >> 1) * 8 + lr;
    const int b_cu_off  = (sub & 1);

    for (int c = 0; c < NCHUNK; c++) {
        const uint32_t st = base + (uint32_t)(c & 1) * STAGE_B;
        if (c < NCHUNK - 1) asm volatile("cp.async.wait_group 1;" ::: "memory");
        else                asm volatile("cp.async.wait_group 0;" ::: "memory");
        __syncthreads();

        #pragma unroll
        for (int ks = 0; ks < 2; ks++) {
            uint32_t aF[4][4];
            #pragma unroll
            for (int mt = 0; mt < 4; mt++) {
                uint32_t off = SWZ((uint32_t)((wm + mt*16 + a_row_off) * 64
                                              + (ks*2 + a_cu_off) * 16));
                ldm_x4(aF[mt][0], aF[mt][1], aF[mt][2], aF[mt][3], st + ST_A + off);
            }
            #pragma unroll
            for (int np = 0; np < 2; np++) {
                uint32_t bH[2][2], bL[2][2];
                uint32_t off = SWZ((uint32_t)((wn + np*16 + b_row_off) * 64
                                              + (ks*2 + b_cu_off) * 16));
                ldm_x4(bH[0][0], bH[0][1], bH[1][0], bH[1][1], st + ST_BH + off);
                ldm_x4(bL[0][0], bL[0][1], bL[1][0], bL[1][1], st + ST_BL + off);
                #pragma unroll
                for (int mt = 0; mt < 4; mt++)
                    #pragma unroll
                    for (int nh = 0; nh < 2; nh++)
                        mma16816h(acc[mt][np*2 + nh], aF[mt], bH[nh]);
                #pragma unroll
                for (int mt = 0; mt < 4; mt++)
                    #pragma unroll
                    for (int nh = 0; nh < 2; nh++)
                        mma16816h(acc[mt][np*2 + nh], aF[mt], bL[nh]);
            }
        }
        __syncthreads();
        if (c + 2 < NCHUNK) load_chunk(c + 2, st);
    }

    const int q = lane >> 2;
    const int i2 = (lane & 3) * 2;
    #pragma unroll
    for (int mt = 0; mt < 4; mt++) {
        #pragma unroll
        for (int nt = 0; nt < 4; nt++) {
            int m0 = bm + wm + mt*16 + q;
            int n0 = bn + wn + nt*8 + i2;
            float2 bv = *(const float2*)(bias + n0);
            float v00 = acc[mt][nt][0] + bv.x, v01 = acc[mt][nt][1] + bv.y;
            float v10 = acc[mt][nt][2] + bv.x, v11 = acc[mt][nt][3] + bv.y;
            __nv_bfloat16 h00 = __float2bfloat16(v00), h01 = __float2bfloat16(v01);
            __nv_bfloat16 h10 = __float2bfloat16(v10), h11 = __float2bfloat16(v11);
            __nv_bfloat16 l00 = __float2bfloat16(v00 - __bfloat162float(h00));
            __nv_bfloat16 l01 = __float2bfloat16(v01 - __bfloat162float(h01));
            __nv_bfloat16 l10 = __float2bfloat16(v10 - __bfloat162float(h10));
            __nv_bfloat16 l11 = __float2bfloat16(v11 - __bfloat162float(h11));
            *(__nv_bfloat162*)(Gh + (size_t)m0 * GOUT + n0)     = __nv_bfloat162(h00, h01);
            *(__nv_bfloat162*)(Gh + (size_t)(m0+8) * GOUT + n0) = __nv_bfloat162(h10, h11);
            *(__nv_bfloat162*)(Gl + (size_t)m0 * GOUT + n0)     = __nv_bfloat162(l00, l01);
            *(__nv_bfloat162*)(Gl + (size_t)(m0+8) * GOUT + n0) = __nv_bfloat162(l10, l11);
        }
    }
}

// ---------------- q/k GEMM: 64x64 tile, split-bf16 mma (3-term) --------------
#define QK_BK 64
#define QK_NCH (CIN / QK_BK)
#define QK_AH 0
#define QK_AL 8192
#define QK_BH 16384
#define QK_BL 24576
#define QK_STAGE 32768
#define SMEM_QK (1024 + 2 * QK_STAGE)

__global__ void __launch_bounds__(128, 1)
qk_gemm_mma(const __nv_bfloat16* __restrict__ X1h, const __nv_bfloat16* __restrict__ X1l,
            const __nv_bfloat16* __restrict__ X2h, const __nv_bfloat16* __restrict__ X2l,
            const __nv_bfloat16* __restrict__ W1h, const __nv_bfloat16* __restrict__ W1l,
            const __nv_bfloat16* __restrict__ W2h, const __nv_bfloat16* __restrict__ W2l,
            const float* __restrict__ b1, const float* __restrict__ b2,
            float* __restrict__ Q, float* __restrict__ K)
{
    extern __shared__ char smem_raw[];
    const uint32_t base = (smem_u32(smem_raw) + 1023u) & ~1023u;

    const int sel = blockIdx.y;
    const __nv_bfloat16* Ah = sel ? X2h : X1h;
    const __nv_bfloat16* Al = sel ? X2l : X1l;
    const __nv_bfloat16* Bh = sel ? W2h : W1h;
    const __nv_bfloat16* Bl = sel ? W2l : W1l;
    const float* bias = sel ? b2 : b1;
    float* C = sel ? K : Q;

    const int tid  = threadIdx.x;
    const int wid  = tid >> 5;
    const int lane = tid & 31;
    const int bm = blockIdx.x * 64;
    const int wm = (wid >> 1) * 32;
    const int wn = (wid & 1) * 32;

    auto load_chunk = [&](int c, uint32_t st) {
        const int k0 = c * QK_BK;
        #pragma unroll
        for (int i = 0; i < 4; i++) {
            int u   = tid + i * 128;
            int row = u >> 3;
            int ku  = u & 7;
            uint32_t so = SWZ((uint32_t)(row * 128 + ku * 16));
            size_t ga = (size_t)(bm + row) * CIN + k0 + ku * 8;
            size_t gb = (size_t)row * CIN + k0 + ku * 8;
            cp_async16(st + QK_AH + so, Ah + ga);
            cp_async16(st + QK_AL + so, Al + ga);
            cp_async16(st + QK_BH + so, Bh + gb);
            cp_async16(st + QK_BL + so, Bl + gb);
        }
        asm volatile("cp.async.commit_group;" ::: "memory");
    };

    load_chunk(0, base);
    load_chunk(1, base + QK_STAGE);

    float acc[2][4][4];
    #pragma unroll
    for (int i = 0; i < 2; i++)
        #pragma unroll
        for (int j = 0; j < 4; j++)
            #pragma unroll
            for (int r = 0; r < 4; r++) acc[i][j][r] = 0.f;

    const int sub = lane >> 3;
    const int lr  = lane & 7;
    const int a_row_off = (sub & 1) * 8 + lr;
    const int a_cu_off  = (sub >> 1);
    const int b_row_off = (sub >> 1) * 8 + lr;
    const int b_cu_off  = (sub & 1);

    for (int c = 0; c < QK_NCH; c++) {
        const uint32_t st = base + (uint32_t)(c & 1) * QK_STAGE;
        if (c < QK_NCH - 1) asm volatile("cp.async.wait_group 1;" ::: "memory");
        else                asm volatile("cp.async.wait_group 0;" ::: "memory");
        __syncthreads();

        #pragma unroll
        for (int ks = 0; ks < 4; ks++) {
            uint32_t aH[2][4], aL[2][4], bH[4][2], bL[4][2];
            #pragma unroll
            for (int mt = 0; mt < 2; mt++) {
                uint32_t off = SWZ((uint32_t)((wm + mt*16 + a_row_off) * 128
                                              + (ks*2 + a_cu_off) * 16));
                ldm_x4(aH[mt][0], aH[mt][1], aH[mt][2], aH[mt][3], st + QK_AH + off);
                ldm_x4(aL[mt][0], aL[mt][1], aL[mt][2], aL[mt][3], st + QK_AL + off);
            }
            #pragma unroll
            for (int np = 0; np < 2; np++) {
                uint32_t off = SWZ((uint32_t)((wn + np*16 + b_row_off) * 128
                                              + (ks*2 + b_cu_off) * 16));
                ldm_x4(bH[2*np][0], bH[2*np][1], bH[2*np+1][0], bH[2*np+1][1],
                       st + QK_BH + off);
                ldm_x4(bL[2*np][0], bL[2*np][1], bL[2*np+1][0], bL[2*np+1][1],
                       st + QK_BL + off);
            }
            #pragma unroll
            for (int mt = 0; mt < 2; mt++)
                #pragma unroll
                for (int nt = 0; nt < 4; nt++)
                    mma16816(acc[mt][nt], aH[mt], bH[nt]);
            #pragma unroll
            for (int mt = 0; mt < 2; mt++)
                #pragma unroll
                for (int nt = 0; nt < 4; nt++)
                    mma16816(acc[mt][nt], aH[mt], bL[nt]);
            #pragma unroll
            for (int mt = 0; mt < 2; mt++)
                #pragma unroll
                for (int nt = 0; nt < 4; nt++)
                    mma16816(acc[mt][nt], aL[mt], bH[nt]);
        }
        __syncthreads();
        if (c + 2 < QK_NCH) load_chunk(c + 2, st);
    }

    const int q = lane >> 2;
    const int i2 = (lane & 3) * 2;
    #pragma unroll
    for (int mt = 0; mt < 2; mt++) {
        #pragma unroll
        for (int nt = 0; nt < 4; nt++) {
            int m0 = bm + wm + mt*16 + q;
            int n0 = wn + nt*8 + i2;
            float2 bv = *(const float2*)(bias + n0);
            float2 o0 = { acc[mt][nt][0] + bv.x, acc[mt][nt][1] + bv.y };
            float2 o1 = { acc[mt][nt][2] + bv.x, acc[mt][nt][3] + bv.y };
            *(float2*)(C + (size_t)m0 * NF + n0)     = o0;
            *(float2*)(C + (size_t)(m0+8) * NF + n0) = o1;
        }
    }
}

// ---------------- scores + fused activation -> act hi/lo ---------------------
__global__ void __launch_bounds__(512)
scores_act_kernel(const float* __restrict__ actw,
                  const float* __restrict__ qb,
                  const float* __restrict__ kb,
                  __nv_bfloat16* __restrict__ ah,
                  __nv_bfloat16* __restrict__ al)
{
    const int b  = blockIdx.x;
    const int s  = blockIdx.y * 32 + (threadIdx.x >> 4);
    const int tp = threadIdx.x & 15;

    __shared__ float qs[TT * NF];
    for (int idx = threadIdx.x; idx < TT*NF; idx += 512)
        qs[idx] = qb[(size_t)b*TT*NF + idx];

    float kr[NF];
    #pragma unroll
    for (int f = 0; f < NF; ++f) kr[f] = kb[((size_t)b*TT + s)*NF + f];
    __syncthreads();

    float col[8];
    float mx = -1e30f;
    #pragma unroll
    for (int i = 0; i < 8; ++i) {
        const float* qrow = qs + (tp*8 + i)*NF;
        float v = 0.f;
        #pragma unroll
        for (int f = 0; f < NF; ++f) v = fmaf(qrow[f], kr[f], v);
        col[i] = v;
        mx = fmaxf(mx, v);
    }
    #pragma unroll
    for (int d = 1; d < 16; d <<= 1)
        mx = fmaxf(mx, __shfl_xor_sync(0xffffffffu, mx, d));
    float sum = 0.f;
    #pragma unroll
    for (int i = 0; i < 8; ++i) sum += expf(col[i] - mx);
    #pragma unroll
    for (int d = 1; d < 16; d <<= 1)
        sum += __shfl_xor_sync(0xffffffffu, sum, d);
    const float inv = 1.f / sum;
    const float w0 = actw[0], w1 = actw[1], w2 = actw[2];
    __nv_bfloat16* ph = ah + (size_t)b*TT*TT + s;
    __nv_bfloat16* pl = al + (size_t)b*TT*TT + s;
    #pragma unroll
    for (int i = 0; i < 8; ++i) {
        int t = tp*8 + i;
        float v = col[i];
        float a = w0 * fmaxf(v, 0.f)
                + w1 * (1.f / (1.f + expf(-v)))
                + w2 * (expf(v - mx) * inv);
        __nv_bfloat16 h = __float2bfloat16(a);
        __nv_bfloat16 l = __float2bfloat16(a - __bfloat162float(h));
        ph[t*TT] = h;
        pl[t*TT] = l;
    }
}

// ---------------- out GEMM: out[b] = act[b] @ g[b]  (K=128) -------------------
#define OROW 272
#define O_AH 0
#define O_AL (128 * OROW)
#define O_BH (2 * 128 * OROW)
#define O_BL (3 * 128 * OROW)
#define SMEM_OUT (4 * 128 * OROW + 1024)

__global__ void __launch_bounds__(256, 1)
out_gemm_mma(const __nv_bfloat16* __restrict__ AHg, const __nv_bfloat16* __restrict__ ALg,
             const __nv_bfloat16* __restrict__ GH, const __nv_bfloat16* __restrict__ GL,
             float* __restrict__ Out)
{
    extern __shared__ char smem_raw[];
    const uint32_t base = (smem_u32(smem_raw) + 1023u) & ~1023u;

    const int tid  = threadIdx.x;
    const int wid  = tid >> 5;
    const int lane = tid & 31;
    const int b  = blockIdx.y;
    const int bn = blockIdx.x * 128;
    const int wm = (wid >> 2) * 64;
    const int wn = (wid & 3) * 32;

    #pragma unroll
    for (int i = 0; i < 8; i++) {
        int u   = tid + i * 256;
        int row = u >> 4;
        int cu  = u & 15;
        uint32_t so = (uint32_t)(row * OROW + cu * 16);
        size_t ga = ((size_t)b*TT + row) * TT + cu * 8;
        size_t gb = ((size_t)b*TT + row) * GOUT + bn + cu * 8;
        cp_async16(base + O_AH + so, AHg + ga);
        cp_async16(base + O_AL + so, ALg + ga);
        cp_async16(base + O_BH + so, GH + gb);
        cp_async16(base + O_BL + so, GL + gb);
    }
    asm volatile("cp.async.commit_group;" ::: "memory");
    asm volatile("cp.async.wait_group 0;" ::: "memory");
    __syncthreads();

    float acc[4][4][4];
    #pragma unroll
    for (int i = 0; i < 4; i++)
        #pragma unroll
        for (int j = 0; j < 4; j++)
            #pragma unroll
            for (int r = 0; r < 4; r++) acc[i][j][r] = 0.f;

    const int sub = lane >> 3;
    const int lr  = lane & 7;
    const int a_row_off = (sub & 1) * 8 + lr;
    const int a_cu_off  = (sub >> 1);
    const int bt_row_off = (sub & 1) * 8 + lr;
    const int bt_cu_off  = (sub >> 1);

    #pragma unroll
    for (int ks = 0; ks < 8; ks++) {
        uint32_t aH[4][4], aL[4][4], bH[4][2], bL[4][2];
        #pragma unroll
        for (int mt = 0; mt < 4; mt++) {
            uint32_t off = (uint32_t)((wm + mt*16 + a_row_off) * OROW
                                      + ks*32 + a_cu_off * 16);
            ldm_x4(aH[mt][0], aH[mt][1], aH[mt][2], aH[mt][3], base + O_AH + off);
            ldm_x4(aL[mt][0], aL[mt][1], aL[mt][2], aL[mt][3], base + O_AL + off);
        }
        #pragma unroll
        for (int np = 0; np < 2; np++) {
            int n0 = wn + np*16;
            uint32_t off = (uint32_t)((ks*16 + bt_row_off) * OROW
                                      + n0*2 + bt_cu_off * 16);
            ldm_x4_t(bH[2*np][0], bH[2*np][1], bH[2*np+1][0], bH[2*np+1][1],
                     base + O_BH + off);
            ldm_x4_t(bL[2*np][0], bL[2*np][1], bL[2*np+1][0], bL[2*np+1][1],
                     base + O_BL + off);
        }
        #pragma unroll
        for (int mt = 0; mt < 4; mt++)
            #pragma unroll
            for (int nt = 0; nt < 4; nt++)
                mma16816(acc[mt][nt], aH[mt], bH[nt]);
        #pragma unroll
        for (int mt = 0; mt < 4; mt++)
            #pragma unroll
            for (int nt = 0; nt < 4; nt++)
                mma16816(acc[mt][nt], aH[mt], bL[nt]);
        #pragma unroll
        for (int mt = 0; mt < 4; mt++)
            #pragma unroll
            for (int nt = 0; nt < 4; nt++)
                mma16816(acc[mt][nt], aL[mt], bH[nt]);
    }

    const int q = lane >> 2;
    const int i2 = (lane & 3) * 2;
    #pragma unroll
    for (int mt = 0; mt < 4; mt++) {
        #pragma unroll
        for (int nt = 0; nt < 4; nt++) {
            int m0 = wm + mt*16 + q;
            int n0 = bn + wn + nt*8 + i2;
            float2 o0 = { acc[mt][nt][0], acc[mt][nt][1] };
            float2 o1 = { acc[mt][nt][2], acc[mt][nt][3] };
            *(float2*)(Out + ((size_t)b*TT + m0) * GOUT + n0)     = o0;
            *(float2*)(Out + ((size_t)b*TT + m0 + 8) * GOUT + n0) = o1;
        }
    }
}

// ---------------------------------------------------------------------------
extern "C" void kernel_launch(void* const* d_in, const int* in_sizes, int n_in,
                              void* d_out, int out_size)
{
    const float* x1   = (const float*)d_in[0];
    const float* x2   = (const float*)d_in[1];
    const float* actw = (const float*)d_in[2];
    const float* w1   = (const float*)d_in[3];
    const float* b1   = (const float*)d_in[4];
    const float* w2   = (const float*)d_in[5];
    const float* b2   = (const float*)d_in[6];
    const float* wg   = (const float*)d_in[7];
    const float* bg   = (const float*)d_in[8];
    float* out = (float*)d_out;

    float *qp, *kp;
    __nv_bfloat16 *ahp, *alp, *x2hp, *x2lp;
    __nv_bfloat16 *w1hp, *w1lp, *w2hp, *w2lp, *ghp, *glp, *acthp, *actlp;
    __half *x1fp, *wghp, *wglp;
    cudaGetSymbolAddress((void**)&qp, q_buf);
    cudaGetSymbolAddress((void**)&kp, k_buf);
    cudaGetSymbolAddress((void**)&ahp, a_hi);
    cudaGetSymbolAddress((void**)&alp, a_lo);
    cudaGetSymbolAddress((void**)&x2hp, x2h);
    cudaGetSymbolAddress((void**)&x2lp, x2l);
    cudaGetSymbolAddress((void**)&x1fp, x1f);
    cudaGetSymbolAddress((void**)&wghp, wgh);
    cudaGetSymbolAddress((void**)&wglp, wgl);
    cudaGetSymbolAddress((void**)&w1hp, w1h);
    cudaGetSymbolAddress((void**)&w1lp, w1l);
    cudaGetSymbolAddress((void**)&w2hp, w2h);
    cudaGetSymbolAddress((void**)&w2lp, w2l);
    cudaGetSymbolAddress((void**)&ghp, g_h);
    cudaGetSymbolAddress((void**)&glp, g_l);
    cudaGetSymbolAddress((void**)&acthp, act_h);
    cudaGetSymbolAddress((void**)&actlp, act_l);

    cudaFuncSetAttribute(g_gemm_mma, cudaFuncAttributeMaxDynamicSharedMemorySize, SMEM_G);
    cudaFuncSetAttribute(qk_gemm_mma, cudaFuncAttributeMaxDynamicSharedMemorySize, SMEM_QK);
    cudaFuncSetAttribute(out_gemm_mma, cudaFuncAttributeMaxDynamicSharedMemorySize, SMEM_OUT);

    // conversions
    {
        int n4 = (BT * CIN) / 4;
        split_bf16<<<(n4 + 255) / 256, 256>>>(x1, ahp, alp, n4);      // qk path
        split_bf16<<<(n4 + 255) / 256, 256>>>(x2, x2hp, x2lp, n4);    // qk path
        conv_f16 <<<(n4 + 255) / 256, 256>>>(x1, x1fp, n4);           // g A
        split_f16<<<(n4 + 255) / 256, 256>>>(wg, wghp, wglp, n4);     // g B
        int w4 = (NF * CIN) / 4;
        split_bf16<<<(w4 + 255) / 256, 256>>>(w1, w1hp, w1lp, w4);
        split_bf16<<<(w4 + 255) / 256, 256>>>(w2, w2hp, w2lp, w4);
    }

    // q and k projections
    qk_gemm_mma<<<dim3(BT/64, 2), 128, SMEM_QK>>>(ahp, alp, x2hp, x2lp,
                                                  w1hp, w1lp, w2hp, w2lp,
                                                  b1, b2, qp, kp);

    // g = fp16(x1) @ wg^T + bg -> bf16 hi/lo  (2-term fp16 split)
    g_gemm_mma<<<dim3(GOUT/128, BT/128), 256, SMEM_G>>>(x1fp, wghp, wglp, bg, ghp, glp);

    // scores -> fused activation -> act hi/lo
    scores_act_kernel<<<dim3(NB, 4), 512>>>(actw, qp, kp, acthp, actlp);

    // out[b] = act[b] @ g[b]
    out_gemm_mma<<<dim3(GOUT/128, NB), 256, SMEM_OUT>>>(acthp, actlp, ghp, glp, out);
}

// round 8
// speedup vs baseline: 2.0867x; 1.6196x over previous
#include <cuda_runtime.h>
#include <cuda_bf16.h>
#include <cuda_fp16.h>
#include <math.h>
#include <stdint.h>

#define NB   32
#define TT   128
#define BT   4096
#define CIN  4096
#define NF   64
#define GOUT 4096

// ---------------- scratch (device globals; no allocation allowed) ----------
__device__ float q_buf[(size_t)NB * TT * NF];
__device__ float k_buf[(size_t)NB * TT * NF];
__device__ __align__(1024) __nv_bfloat16 a_hi[(size_t)BT * CIN];     // x1 bf16 split (qk)
__device__ __align__(1024) __nv_bfloat16 a_lo[(size_t)BT * CIN];
__device__ __align__(1024) __nv_bfloat16 x2h[(size_t)BT * CIN];      // x2 bf16 split (qk)
__device__ __align__(1024) __nv_bfloat16 x2l[(size_t)BT * CIN];
__device__ __align__(1024) __half       x1f[(size_t)BT * CIN];       // x1 fp16 (g A)
__device__ __align__(1024) __half       wgf[(size_t)GOUT * CIN];     // wg fp16 (g B)
__device__ __align__(1024) __half       g_f[(size_t)BT * GOUT];      // g fp16
__device__ __align__(1024) __half       act_f[(size_t)NB * TT * TT]; // act fp16
__device__ __align__(1024) __nv_bfloat16 w1h[(size_t)NF * CIN];
__device__ __align__(1024) __nv_bfloat16 w1l[(size_t)NF * CIN];
__device__ __align__(1024) __nv_bfloat16 w2h[(size_t)NF * CIN];
__device__ __align__(1024) __nv_bfloat16 w2l[(size_t)NF * CIN];

// ---------------- small PTX helpers ----------------------------------------
__device__ __forceinline__ uint32_t smem_u32(const void* p) {
    uint32_t a;
    asm("{ .reg .u64 t; cvta.to.shared.u64 t, %1; cvt.u32.u64 %0, t; }" : "=r"(a) : "l"(p));
    return a;
}
__device__ __forceinline__ void cp_async16(uint32_t dst, const void* src) {
    asm volatile("cp.async.cg.shared.global [%0], [%1], 16;" :: "r"(dst), "l"(src) : "memory");
}
__device__ __forceinline__ void ldm_x4(uint32_t& r0, uint32_t& r1, uint32_t& r2, uint32_t& r3,
                                       uint32_t addr) {
    asm volatile("ldmatrix.sync.aligned.m8n8.x4.shared.b16 {%0,%1,%2,%3}, [%4];"
                 : "=r"(r0), "=r"(r1), "=r"(r2), "=r"(r3) : "r"(addr));
}
__device__ __forceinline__ void ldm_x4_t(uint32_t& r0, uint32_t& r1, uint32_t& r2, uint32_t& r3,
                                         uint32_t addr) {
    asm volatile("ldmatrix.sync.aligned.m8n8.x4.trans.shared.b16 {%0,%1,%2,%3}, [%4];"
                 : "=r"(r0), "=r"(r1), "=r"(r2), "=r"(r3) : "r"(addr));
}
__device__ __forceinline__ void mma16816(float* c, const uint32_t* a, const uint32_t* b) {
    asm volatile("mma.sync.aligned.m16n8k16.row.col.f32.bf16.bf16.f32 "
                 "{%0,%1,%2,%3}, {%4,%5,%6,%7}, {%8,%9}, {%0,%1,%2,%3};"
                 : "+f"(c[0]), "+f"(c[1]), "+f"(c[2]), "+f"(c[3])
                 : "r"(a[0]), "r"(a[1]), "r"(a[2]), "r"(a[3]), "r"(b[0]), "r"(b[1]));
}
__device__ __forceinline__ void mma16816h(float* c, const uint32_t* a, const uint32_t* b) {
    asm volatile("mma.sync.aligned.m16n8k16.row.col.f32.f16.f16.f32 "
                 "{%0,%1,%2,%3}, {%4,%5,%6,%7}, {%8,%9}, {%0,%1,%2,%3};"
                 : "+f"(c[0]), "+f"(c[1]), "+f"(c[2]), "+f"(c[3])
                 : "r"(a[0]), "r"(a[1]), "r"(a[2]), "r"(a[3]), "r"(b[0]), "r"(b[1]));
}
#define SWZ(o) ((o) ^ (((o) >> 3) & 0x70))

// ---------------- conversion kernels -----------------------------------------
__global__ void __launch_bounds__(256)
split_bf16(const float* __restrict__ x, __nv_bfloat16* __restrict__ h,
           __nv_bfloat16* __restrict__ l, int n4)
{
    int i = blockIdx.x * blockDim.x + threadIdx.x;
    if (i >= n4) return;
    float4 v = ((const float4*)x)[i];
    __nv_bfloat16 h0 = __float2bfloat16(v.x);
    __nv_bfloat16 h1 = __float2bfloat16(v.y);
    __nv_bfloat16 h2 = __float2bfloat16(v.z);
    __nv_bfloat16 h3 = __float2bfloat16(v.w);
    __nv_bfloat16 l0 = __float2bfloat16(v.x - __bfloat162float(h0));
    __nv_bfloat16 l1 = __float2bfloat16(v.y - __bfloat162float(h1));
    __nv_bfloat16 l2 = __float2bfloat16(v.z - __bfloat162float(h2));
    __nv_bfloat16 l3 = __float2bfloat16(v.w - __bfloat162float(h3));
    ((__nv_bfloat162*)h)[2*i]   = __nv_bfloat162(h0, h1);
    ((__nv_bfloat162*)h)[2*i+1] = __nv_bfloat162(h2, h3);
    ((__nv_bfloat162*)l)[2*i]   = __nv_bfloat162(l0, l1);
    ((__nv_bfloat162*)l)[2*i+1] = __nv_bfloat162(l2, l3);
}

__global__ void __launch_bounds__(256)
conv_f16(const float* __restrict__ x, __half* __restrict__ h, int n4)
{
    int i = blockIdx.x * blockDim.x + threadIdx.x;
    if (i >= n4) return;
    float4 v = ((const float4*)x)[i];
    ((__half2*)h)[2*i]   = __half2(__float2half_rn(v.x), __float2half_rn(v.y));
    ((__half2*)h)[2*i+1] = __half2(__float2half_rn(v.z), __float2half_rn(v.w));
}

// ---------------- g GEMM: g = fp16(x1) @ fp16(wg)^T + bg -> fp16 -------------
// Pure 1-term fp16, fp32 accum. Tile 128x128, BK=32, 8 warps, 2 CTA/SM.
#define BKC 32
#define NCHUNK (CIN / BKC)
#define ST_A  0
#define ST_B  8192
#define STAGE_B 16384
#define SMEM_G (1024 + 2 * STAGE_B)

__global__ void __launch_bounds__(256, 2)
g_gemm_mma(const __half* __restrict__ A, const __half* __restrict__ B,
           const float* __restrict__ bias, __half* __restrict__ G)
{
    extern __shared__ char smem_raw[];
    const uint32_t base = (smem_u32(smem_raw) + 1023u) & ~1023u;

    const int tid  = threadIdx.x;
    const int wid  = tid >> 5;
    const int lane = tid & 31;
    const int bm = blockIdx.y * 128;
    const int bn = blockIdx.x * 128;
    const int wm = (wid >> 2) * 64;
    const int wn = (wid & 3) * 32;

    auto load_chunk = [&](int c, uint32_t st) {
        const int k0 = c * BKC;
        #pragma unroll
        for (int i = 0; i < 2; i++) {
            int u   = tid + i * 256;
            int row = u >> 2;
            int cu  = u & 3;
            uint32_t so = SWZ((uint32_t)(row * 64 + cu * 16));
            cp_async16(st + ST_A + so, A + (size_t)(bm + row) * CIN + k0 + cu * 8);
            cp_async16(st + ST_B + so, B + (size_t)(bn + row) * CIN + k0 + cu * 8);
        }
        asm volatile("cp.async.commit_group;" ::: "memory");
    };

    load_chunk(0, base);
    load_chunk(1, base + STAGE_B);

    float acc[4][4][4];
    #pragma unroll
    for (int i = 0; i < 4; i++)
        #pragma unroll
        for (int j = 0; j < 4; j++)
            #pragma unroll
            for (int r = 0; r < 4; r++) acc[i][j][r] = 0.f;

    const int sub = lane >> 3;
    const int lr  = lane & 7;
    const int a_row_off = (sub & 1) * 8 + lr;
    const int a_cu_off  = (sub >> 1);
    const int b_row_off = (sub >> 1) * 8 + lr;
    const int b_cu_off  = (sub & 1);

    for (int c = 0; c < NCHUNK; c++) {
        const uint32_t st = base + (uint32_t)(c & 1) * STAGE_B;
        if (c < NCHUNK - 1) asm volatile("cp.async.wait_group 1;" ::: "memory");
        else                asm volatile("cp.async.wait_group 0;" ::: "memory");
        __syncthreads();

        #pragma unroll
        for (int ks = 0; ks < 2; ks++) {
            uint32_t aF[4][4], bF[4][2];
            #pragma unroll
            for (int mt = 0; mt < 4; mt++) {
                uint32_t off = SWZ((uint32_t)((wm + mt*16 + a_row_off) * 64
                                              + (ks*2 + a_cu_off) * 16));
                ldm_x4(aF[mt][0], aF[mt][1], aF[mt][2], aF[mt][3], st + ST_A + off);
            }
            #pragma unroll
            for (int np = 0; np < 2; np++) {
                uint32_t off = SWZ((uint32_t)((wn + np*16 + b_row_off) * 64
                                              + (ks*2 + b_cu_off) * 16));
                ldm_x4(bF[2*np][0], bF[2*np][1], bF[2*np+1][0], bF[2*np+1][1],
                       st + ST_B + off);
            }
            #pragma unroll
            for (int mt = 0; mt < 4; mt++)
                #pragma unroll
                for (int nt = 0; nt < 4; nt++)
                    mma16816h(acc[mt][nt], aF[mt], bF[nt]);
        }
        __syncthreads();
        if (c + 2 < NCHUNK) load_chunk(c + 2, st);
    }

    const int q = lane >> 2;
    const int i2 = (lane & 3) * 2;
    #pragma unroll
    for (int mt = 0; mt < 4; mt++) {
        #pragma unroll
        for (int nt = 0; nt < 4; nt++) {
            int m0 = bm + wm + mt*16 + q;
            int n0 = bn + wn + nt*8 + i2;
            float2 bv = *(const float2*)(bias + n0);
            __half2 o0 = __half2(__float2half_rn(acc[mt][nt][0] + bv.x),
                                 __float2half_rn(acc[mt][nt][1] + bv.y));
            __half2 o1 = __half2(__float2half_rn(acc[mt][nt][2] + bv.x),
                                 __float2half_rn(acc[mt][nt][3] + bv.y));
            *(__half2*)(G + (size_t)m0 * GOUT + n0)     = o0;
            *(__half2*)(G + (size_t)(m0+8) * GOUT + n0) = o1;
        }
    }
}

// ---------------- q/k GEMM: 64x64 tile, split-bf16 mma (3-term) --------------
#define QK_BK 64
#define QK_NCH (CIN / QK_BK)
#define QK_AH 0
#define QK_AL 8192
#define QK_BH 16384
#define QK_BL 24576
#define QK_STAGE 32768
#define SMEM_QK (1024 + 2 * QK_STAGE)

__global__ void __launch_bounds__(128, 1)
qk_gemm_mma(const __nv_bfloat16* __restrict__ X1h, const __nv_bfloat16* __restrict__ X1l,
            const __nv_bfloat16* __restrict__ X2h, const __nv_bfloat16* __restrict__ X2l,
            const __nv_bfloat16* __restrict__ W1h, const __nv_bfloat16* __restrict__ W1l,
            const __nv_bfloat16* __restrict__ W2h, const __nv_bfloat16* __restrict__ W2l,
            const float* __restrict__ b1, const float* __restrict__ b2,
            float* __restrict__ Q, float* __restrict__ K)
{
    extern __shared__ char smem_raw[];
    const uint32_t base = (smem_u32(smem_raw) + 1023u) & ~1023u;

    const int sel = blockIdx.y;
    const __nv_bfloat16* Ah = sel ? X2h : X1h;
    const __nv_bfloat16* Al = sel ? X2l : X1l;
    const __nv_bfloat16* Bh = sel ? W2h : W1h;
    const __nv_bfloat16* Bl = sel ? W2l : W1l;
    const float* bias = sel ? b2 : b1;
    float* C = sel ? K : Q;

    const int tid  = threadIdx.x;
    const int wid  = tid >> 5;
    const int lane = tid & 31;
    const int bm = blockIdx.x * 64;
    const int wm = (wid >> 1) * 32;
    const int wn = (wid & 1) * 32;

    auto load_chunk = [&](int c, uint32_t st) {
        const int k0 = c * QK_BK;
        #pragma unroll
        for (int i = 0; i < 4; i++) {
            int u   = tid + i * 128;
            int row = u >> 3;
            int ku  = u & 7;
            uint32_t so = SWZ((uint32_t)(row * 128 + ku * 16));
            size_t ga = (size_t)(bm + row) * CIN + k0 + ku * 8;
            size_t gb = (size_t)row * CIN + k0 + ku * 8;
            cp_async16(st + QK_AH + so, Ah + ga);
            cp_async16(st + QK_AL + so, Al + ga);
            cp_async16(st + QK_BH + so, Bh + gb);
            cp_async16(st + QK_BL + so, Bl + gb);
        }
        asm volatile("cp.async.commit_group;" ::: "memory");
    };

    load_chunk(0, base);
    load_chunk(1, base + QK_STAGE);

    float acc[2][4][4];
    #pragma unroll
    for (int i = 0; i < 2; i++)
        #pragma unroll
        for (int j = 0; j < 4; j++)
            #pragma unroll
            for (int r = 0; r < 4; r++) acc[i][j][r] = 0.f;

    const int sub = lane >> 3;
    const int lr  = lane & 7;
    const int a_row_off = (sub & 1) * 8 + lr;
    const int a_cu_off  = (sub >> 1);
    const int b_row_off = (sub >> 1) * 8 + lr;
    const int b_cu_off  = (sub & 1);

    for (int c = 0; c < QK_NCH; c++) {
        const uint32_t st = base + (uint32_t)(c & 1) * QK_STAGE;
        if (c < QK_NCH - 1) asm volatile("cp.async.wait_group 1;" ::: "memory");
        else                asm volatile("cp.async.wait_group 0;" ::: "memory");
        __syncthreads();

        #pragma unroll
        for (int ks = 0; ks < 4; ks++) {
            uint32_t aH[2][4], aL[2][4], bH[4][2], bL[4][2];
            #pragma unroll
            for (int mt = 0; mt < 2; mt++) {
                uint32_t off = SWZ((uint32_t)((wm + mt*16 + a_row_off) * 128
                                              + (ks*2 + a_cu_off) * 16));
                ldm_x4(aH[mt][0], aH[mt][1], aH[mt][2], aH[mt][3], st + QK_AH + off);
                ldm_x4(aL[mt][0], aL[mt][1], aL[mt][2], aL[mt][3], st + QK_AL + off);
            }
            #pragma unroll
            for (int np = 0; np < 2; np++) {
                uint32_t off = SWZ((uint32_t)((wn + np*16 + b_row_off) * 128
                                              + (ks*2 + b_cu_off) * 16));
                ldm_x4(bH[2*np][0], bH[2*np][1], bH[2*np+1][0], bH[2*np+1][1],
                       st + QK_BH + off);
                ldm_x4(bL[2*np][0], bL[2*np][1], bL[2*np+1][0], bL[2*np+1][1],
                       st + QK_BL + off);
            }
            #pragma unroll
            for (int mt = 0; mt < 2; mt++)
                #pragma unroll
                for (int nt = 0; nt < 4; nt++)
                    mma16816(acc[mt][nt], aH[mt], bH[nt]);
            #pragma unroll
            for (int mt = 0; mt < 2; mt++)
                #pragma unroll
                for (int nt = 0; nt < 4; nt++)
                    mma16816(acc[mt][nt], aH[mt], bL[nt]);
            #pragma unroll
            for (int mt = 0; mt < 2; mt++)
                #pragma unroll
                for (int nt = 0; nt < 4; nt++)
                    mma16816(acc[mt][nt], aL[mt], bH[nt]);
        }
        __syncthreads();
        if (c + 2 < QK_NCH) load_chunk(c + 2, st);
    }

    const int q = lane >> 2;
    const int i2 = (lane & 3) * 2;
    #pragma unroll
    for (int mt = 0; mt < 2; mt++) {
        #pragma unroll
        for (int nt = 0; nt < 4; nt++) {
            int m0 = bm + wm + mt*16 + q;
            int n0 = wn + nt*8 + i2;
            float2 bv = *(const float2*)(bias + n0);
            float2 o0 = { acc[mt][nt][0] + bv.x, acc[mt][nt][1] + bv.y };
            float2 o1 = { acc[mt][nt][2] + bv.x, acc[mt][nt][3] + bv.y };
            *(float2*)(C + (size_t)m0 * NF + n0)     = o0;
            *(float2*)(C + (size_t)(m0+8) * NF + n0) = o1;
        }
    }
}

// ---------------- scores + fused activation -> act fp16 ----------------------
__global__ void __launch_bounds__(512)
scores_act_kernel(const float* __restrict__ actw,
                  const float* __restrict__ qb,
                  const float* __restrict__ kb,
                  __half* __restrict__ af)
{
    const int b  = blockIdx.x;
    const int s  = blockIdx.y * 32 + (threadIdx.x >> 4);
    const int tp = threadIdx.x & 15;

    __shared__ float qs[TT * NF];
    for (int idx = threadIdx.x; idx < TT*NF; idx += 512)
        qs[idx] = qb[(size_t)b*TT*NF + idx];

    float kr[NF];
    #pragma unroll
    for (int f = 0; f < NF; ++f) kr[f] = kb[((size_t)b*TT + s)*NF + f];
    __syncthreads();

    float col[8];
    float mx = -1e30f;
    #pragma unroll
    for (int i = 0; i < 8; ++i) {
        const float* qrow = qs + (tp*8 + i)*NF;
        float v = 0.f;
        #pragma unroll
        for (int f = 0; f < NF; ++f) v = fmaf(qrow[f], kr[f], v);
        col[i] = v;
        mx = fmaxf(mx, v);
    }
    #pragma unroll
    for (int d = 1; d < 16; d <<= 1)
        mx = fmaxf(mx, __shfl_xor_sync(0xffffffffu, mx, d));
    float sum = 0.f;
    #pragma unroll
    for (int i = 0; i < 8; ++i) sum += expf(col[i] - mx);
    #pragma unroll
    for (int d = 1; d < 16; d <<= 1)
        sum += __shfl_xor_sync(0xffffffffu, sum, d);
    const float inv = 1.f / sum;
    const float w0 = actw[0], w1 = actw[1], w2 = actw[2];
    __half* pf = af + (size_t)b*TT*TT + s;
    #pragma unroll
    for (int i = 0; i < 8; ++i) {
        int t = tp*8 + i;
        float v = col[i];
        float a = w0 * fmaxf(v, 0.f)
                + w1 * (1.f / (1.f + expf(-v)))
                + w2 * (expf(v - mx) * inv);
        pf[t*TT] = __float2half_rn(a);
    }
}

// ---------------- out GEMM: out[b] = act[b] @ g[b]  (pure fp16, K=128) -------
#define OROW 272
#define O_A 0
#define O_B (128 * OROW)
#define SMEM_OUT (2 * 128 * OROW + 1024)

__global__ void __launch_bounds__(256, 2)
out_gemm_mma(const __half* __restrict__ Af, const __half* __restrict__ Gf,
             float* __restrict__ Out)
{
    extern __shared__ char smem_raw[];
    const uint32_t base = (smem_u32(smem_raw) + 1023u) & ~1023u;

    const int tid  = threadIdx.x;
    const int wid  = tid >> 5;
    const int lane = tid & 31;
    const int b  = blockIdx.y;
    const int bn = blockIdx.x * 128;
    const int wm = (wid >> 2) * 64;
    const int wn = (wid & 3) * 32;

    #pragma unroll
    for (int i = 0; i < 8; i++) {
        int u   = tid + i * 256;
        int row = u >> 4;
        int cu  = u & 15;
        uint32_t so = (uint32_t)(row * OROW + cu * 16);
        cp_async16(base + O_A + so, Af + ((size_t)b*TT + row) * TT + cu * 8);
        cp_async16(base + O_B + so, Gf + ((size_t)b*TT + row) * GOUT + bn + cu * 8);
    }
    asm volatile("cp.async.commit_group;" ::: "memory");
    asm volatile("cp.async.wait_group 0;" ::: "memory");
    __syncthreads();

    float acc[4][4][4];
    #pragma unroll
    for (int i = 0; i < 4; i++)
        #pragma unroll
        for (int j = 0; j < 4; j++)
            #pragma unroll
            for (int r = 0; r < 4; r++) acc[i][j][r] = 0.f;

    const int sub = lane >> 3;
    const int lr  = lane & 7;
    const int a_row_off = (sub & 1) * 8 + lr;
    const int a_cu_off  = (sub >> 1);
    const int bt_row_off = (sub & 1) * 8 + lr;
    const int bt_cu_off  = (sub >> 1);

    #pragma unroll
    for (int ks = 0; ks < 8; ks++) {
        uint32_t aF[4][4], bF[4][2];
        #pragma unroll
        for (int mt = 0; mt < 4; mt++) {
            uint32_t off = (uint32_t)((wm + mt*16 + a_row_off) * OROW
                                      + ks*32 + a_cu_off * 16);
            ldm_x4(aF[mt][0], aF[mt][1], aF[mt][2], aF[mt][3], base + O_A + off);
        }
        #pragma unroll
        for (int np = 0; np < 2; np++) {
            int n0 = wn + np*16;
            uint32_t off = (uint32_t)((ks*16 + bt_row_off) * OROW
                                      + n0*2 + bt_cu_off * 16);
            ldm_x4_t(bF[2*np][0], bF[2*np][1], bF[2*np+1][0], bF[2*np+1][1],
                     base + O_B + off);
        }
        #pragma unroll
        for (int mt = 0; mt < 4; mt++)
            #pragma unroll
            for (int nt = 0; nt < 4; nt++)
                mma16816h(acc[mt][nt], aF[mt], bF[nt]);
    }

    const int q = lane >> 2;
    const int i2 = (lane & 3) * 2;
    #pragma unroll
    for (int mt = 0; mt < 4; mt++) {
        #pragma unroll
        for (int nt = 0; nt < 4; nt++) {
            int m0 = wm + mt*16 + q;
            int n0 = bn + wn + nt*8 + i2;
            float2 o0 = { acc[mt][nt][0], acc[mt][nt][1] };
            float2 o1 = { acc[mt][nt][2], acc[mt][nt][3] };
            *(float2*)(Out + ((size_t)b*TT + m0) * GOUT + n0)     = o0;
            *(float2*)(Out + ((size_t)b*TT + m0 + 8) * GOUT + n0) = o1;
        }
    }
}

// ---------------------------------------------------------------------------
extern "C" void kernel_launch(void* const* d_in, const int* in_sizes, int n_in,
                              void* d_out, int out_size)
{
    const float* x1   = (const float*)d_in[0];
    const float* x2   = (const float*)d_in[1];
    const float* actw = (const float*)d_in[2];
    const float* w1   = (const float*)d_in[3];
    const float* b1   = (const float*)d_in[4];
    const float* w2   = (const float*)d_in[5];
    const float* b2   = (const float*)d_in[6];
    const float* wg   = (const float*)d_in[7];
    const float* bg   = (const float*)d_in[8];
    float* out = (float*)d_out;

    float *qp, *kp;
    __nv_bfloat16 *ahp, *alp, *x2hp, *x2lp;
    __nv_bfloat16 *w1hp, *w1lp, *w2hp, *w2lp;
    __half *x1fp, *wgfp, *gfp, *actfp;
    cudaGetSymbolAddress((void**)&qp, q_buf);
    cudaGetSymbolAddress((void**)&kp, k_buf);
    cudaGetSymbolAddress((void**)&ahp, a_hi);
    cudaGetSymbolAddress((void**)&alp, a_lo);
    cudaGetSymbolAddress((void**)&x2hp, x2h);
    cudaGetSymbolAddress((void**)&x2lp, x2l);
    cudaGetSymbolAddress((void**)&x1fp, x1f);
    cudaGetSymbolAddress((void**)&wgfp, wgf);
    cudaGetSymbolAddress((void**)&gfp, g_f);
    cudaGetSymbolAddress((void**)&actfp, act_f);
    cudaGetSymbolAddress((void**)&w1hp, w1h);
    cudaGetSymbolAddress((void**)&w1lp, w1l);
    cudaGetSymbolAddress((void**)&w2hp, w2h);
    cudaGetSymbolAddress((void**)&w2lp, w2l);

    cudaFuncSetAttribute(g_gemm_mma, cudaFuncAttributeMaxDynamicSharedMemorySize, SMEM_G);
    cudaFuncSetAttribute(qk_gemm_mma, cudaFuncAttributeMaxDynamicSharedMemorySize, SMEM_QK);
    cudaFuncSetAttribute(out_gemm_mma, cudaFuncAttributeMaxDynamicSharedMemorySize, SMEM_OUT);

    // conversions
    {
        int n4 = (BT * CIN) / 4;
        split_bf16<<<(n4 + 255) / 256, 256>>>(x1, ahp, alp, n4);      // qk path
        split_bf16<<<(n4 + 255) / 256, 256>>>(x2, x2hp, x2lp, n4);    // qk path
        conv_f16 <<<(n4 + 255) / 256, 256>>>(x1, x1fp, n4);           // g A
        conv_f16 <<<(n4 + 255) / 256, 256>>>(wg, wgfp, n4);           // g B
        int w4 = (NF * CIN) / 4;
        split_bf16<<<(w4 + 255) / 256, 256>>>(w1, w1hp, w1lp, w4);
        split_bf16<<<(w4 + 255) / 256, 256>>>(w2, w2hp, w2lp, w4);
    }

    // q and k projections (bf16 3-term — protects softmax inputs)
    qk_gemm_mma<<<dim3(BT/64, 2), 128, SMEM_QK>>>(ahp, alp, x2hp, x2lp,
                                                  w1hp, w1lp, w2hp, w2lp,
                                                  b1, b2, qp, kp);

    // g = fp16(x1) @ fp16(wg)^T + bg -> fp16 (pure fp16 1-term)
    g_gemm_mma<<<dim3(GOUT/128, BT/128), 256, SMEM_G>>>(x1fp, wgfp, bg, gfp);

    // scores -> fused activation -> act fp16
    scores_act_kernel<<<dim3(NB, 4), 512>>>(actw, qp, kp, actfp);

    // out[b] = act[b] @ g[b]  (pure fp16 1-term)
    out_gemm_mma<<<dim3(GOUT/128, NB), 256, SMEM_OUT>>>(actfp, gfp, out);
}

// round 10
// speedup vs baseline: 2.2825x; 1.0938x over previous
#include <cuda_runtime.h>
#include <cuda_bf16.h>
#include <cuda_fp16.h>
#include <math.h>
#include <stdint.h>

#define NB   32
#define TT   128
#define BT   4096
#define CIN  4096
#define NF   64
#define GOUT 4096

// ---------------- scratch (device globals; no allocation allowed) ----------
__device__ float q_buf[(size_t)NB * TT * NF];
__device__ float k_buf[(size_t)NB * TT * NF];
__device__ __align__(1024) __nv_bfloat16 a_hi[(size_t)BT * CIN];     // x1 bf16 split (qk)
__device__ __align__(1024) __nv_bfloat16 a_lo[(size_t)BT * CIN];
__device__ __align__(1024) __nv_bfloat16 x2h[(size_t)BT * CIN];      // x2 bf16 split (qk)
__device__ __align__(1024) __nv_bfloat16 x2l[(size_t)BT * CIN];
__device__ __align__(1024) __half       x1f[(size_t)BT * CIN];       // x1 fp16 (g A)
__device__ __align__(1024) __half       wgf[(size_t)GOUT * CIN];     // wg fp16 (g B)
__device__ __align__(1024) __half       act_f[(size_t)NB * TT * TT]; // act fp16
__device__ __align__(1024) __nv_bfloat16 w1h[(size_t)NF * CIN];
__device__ __align__(1024) __nv_bfloat16 w1l[(size_t)NF * CIN];
__device__ __align__(1024) __nv_bfloat16 w2h[(size_t)NF * CIN];
__device__ __align__(1024) __nv_bfloat16 w2l[(size_t)NF * CIN];

// ---------------- small PTX helpers ----------------------------------------
__device__ __forceinline__ uint32_t smem_u32(const void* p) {
    uint32_t a;
    asm("{ .reg .u64 t; cvta.to.shared.u64 t, %1; cvt.u32.u64 %0, t; }" : "=r"(a) : "l"(p));
    return a;
}
__device__ __forceinline__ void cp_async16(uint32_t dst, const void* src) {
    asm volatile("cp.async.cg.shared.global [%0], [%1], 16;" :: "r"(dst), "l"(src) : "memory");
}
__device__ __forceinline__ void ldm_x4(uint32_t& r0, uint32_t& r1, uint32_t& r2, uint32_t& r3,
                                       uint32_t addr) {
    asm volatile("ldmatrix.sync.aligned.m8n8.x4.shared.b16 {%0,%1,%2,%3}, [%4];"
                 : "=r"(r0), "=r"(r1), "=r"(r2), "=r"(r3) : "r"(addr));
}
__device__ __forceinline__ void ldm_x4_t(uint32_t& r0, uint32_t& r1, uint32_t& r2, uint32_t& r3,
                                         uint32_t addr) {
    asm volatile("ldmatrix.sync.aligned.m8n8.x4.trans.shared.b16 {%0,%1,%2,%3}, [%4];"
                 : "=r"(r0), "=r"(r1), "=r"(r2), "=r"(r3) : "r"(addr));
}
__device__ __forceinline__ void mma16816(float* c, const uint32_t* a, const uint32_t* b) {
    asm volatile("mma.sync.aligned.m16n8k16.row.col.f32.bf16.bf16.f32 "
                 "{%0,%1,%2,%3}, {%4,%5,%6,%7}, {%8,%9}, {%0,%1,%2,%3};"
                 : "+f"(c[0]), "+f"(c[1]), "+f"(c[2]), "+f"(c[3])
                 : "r"(a[0]), "r"(a[1]), "r"(a[2]), "r"(a[3]), "r"(b[0]), "r"(b[1]));
}
__device__ __forceinline__ void mma16816h(float* c, const uint32_t* a, const uint32_t* b) {
    asm volatile("mma.sync.aligned.m16n8k16.row.col.f32.f16.f16.f32 "
                 "{%0,%1,%2,%3}, {%4,%5,%6,%7}, {%8,%9}, {%0,%1,%2,%3};"
                 : "+f"(c[0]), "+f"(c[1]), "+f"(c[2]), "+f"(c[3])
                 : "r"(a[0]), "r"(a[1]), "r"(a[2]), "r"(a[3]), "r"(b[0]), "r"(b[1]));
}
#define SWZ(o) ((o) ^ (((o) >> 3) & 0x70))

// ---------------- conversion kernels -----------------------------------------
__global__ void __launch_bounds__(256)
conv_x1(const float* __restrict__ x, __nv_bfloat16* __restrict__ h,
        __nv_bfloat16* __restrict__ l, __half* __restrict__ f, int n4)
{
    int i = blockIdx.x * blockDim.x + threadIdx.x;
    if (i >= n4) return;
    float4 v = ((const float4*)x)[i];
    __nv_bfloat16 h0 = __float2bfloat16(v.x);
    __nv_bfloat16 h1 = __float2bfloat16(v.y);
    __nv_bfloat16 h2 = __float2bfloat16(v.z);
    __nv_bfloat16 h3 = __float2bfloat16(v.w);
    ((__nv_bfloat162*)h)[2*i]   = __nv_bfloat162(h0, h1);
    ((__nv_bfloat162*)h)[2*i+1] = __nv_bfloat162(h2, h3);
    ((__nv_bfloat162*)l)[2*i]   = __nv_bfloat162(
        __float2bfloat16(v.x - __bfloat162float(h0)),
        __float2bfloat16(v.y - __bfloat162float(h1)));
    ((__nv_bfloat162*)l)[2*i+1] = __nv_bfloat162(
        __float2bfloat16(v.z - __bfloat162float(h2)),
        __float2bfloat16(v.w - __bfloat162float(h3)));
    ((__half2*)f)[2*i]   = __half2(__float2half_rn(v.x), __float2half_rn(v.y));
    ((__half2*)f)[2*i+1] = __half2(__float2half_rn(v.z), __float2half_rn(v.w));
}

__global__ void __launch_bounds__(256)
split_bf16(const float* __restrict__ x, __nv_bfloat16* __restrict__ h,
           __nv_bfloat16* __restrict__ l, int n4)
{
    int i = blockIdx.x * blockDim.x + threadIdx.x;
    if (i >= n4) return;
    float4 v = ((const float4*)x)[i];
    __nv_bfloat16 h0 = __float2bfloat16(v.x);
    __nv_bfloat16 h1 = __float2bfloat16(v.y);
    __nv_bfloat16 h2 = __float2bfloat16(v.z);
    __nv_bfloat16 h3 = __float2bfloat16(v.w);
    ((__nv_bfloat162*)h)[2*i]   = __nv_bfloat162(h0, h1);
    ((__nv_bfloat162*)h)[2*i+1] = __nv_bfloat162(h2, h3);
    ((__nv_bfloat162*)l)[2*i]   = __nv_bfloat162(
        __float2bfloat16(v.x - __bfloat162float(h0)),
        __float2bfloat16(v.y - __bfloat162float(h1)));
    ((__nv_bfloat162*)l)[2*i+1] = __nv_bfloat162(
        __float2bfloat16(v.z - __bfloat162float(h2)),
        __float2bfloat16(v.w - __bfloat162float(h3)));
}

__global__ void __launch_bounds__(256)
conv_f16(const float* __restrict__ x, __half* __restrict__ h, int n4)
{
    int i = blockIdx.x * blockDim.x + threadIdx.x;
    if (i >= n4) return;
    float4 v = ((const float4*)x)[i];
    ((__half2*)h)[2*i]   = __half2(__float2half_rn(v.x), __float2half_rn(v.y));
    ((__half2*)h)[2*i+1] = __half2(__float2half_rn(v.z), __float2half_rn(v.w));
}

// ---------------- fused g + out GEMM ------------------------------------------
// Phase 1: gtile = fp16(x1[b-block]) @ fp16(wg[bn-block])^T + bg  (K=4096)
// Phase 2: out[b][:, bn:bn+128] = act[b] @ gtile                  (K=128)
#define BKC 32
#define NCHUNK (CIN / BKC)
#define ST_A  0
#define ST_B  8192
#define STAGE_B 16384
#define OROW 272
#define GT_OFF 32768
#define AT_OFF (32768 + 128 * OROW)
#define SMEM_G (1024 + 32768 + 2 * 128 * OROW)

__global__ void __launch_bounds__(256, 2)
g_out_gemm(const __half* __restrict__ A, const __half* __restrict__ B,
           const float* __restrict__ bias, const __half* __restrict__ Act,
           float* __restrict__ Out)
{
    extern __shared__ char smem_raw[];
    const uint32_t base = (smem_u32(smem_raw) + 1023u) & ~1023u;

    const int tid  = threadIdx.x;
    const int wid  = tid >> 5;
    const int lane = tid & 31;
    const int b  = blockIdx.y;          // batch = row-block of g
    const int bm = b * 128;
    const int bn = blockIdx.x * 128;
    const int wm = (wid >> 2) * 64;
    const int wn = (wid & 3) * 32;

    auto load_chunk = [&](int c, uint32_t st) {
        const int k0 = c * BKC;
        #pragma unroll
        for (int i = 0; i < 2; i++) {
            int u   = tid + i * 256;
            int row = u >> 2;
            int cu  = u & 3;
            uint32_t so = SWZ((uint32_t)(row * 64 + cu * 16));
            cp_async16(st + ST_A + so, A + (size_t)(bm + row) * CIN + k0 + cu * 8);
            cp_async16(st + ST_B + so, B + (size_t)(bn + row) * CIN + k0 + cu * 8);
        }
    };

    // chunk 0 + act[b] (ready: scores ran earlier) share the first commit group
    load_chunk(0, base);
    #pragma unroll
    for (int i = 0; i < 8; i++) {
        int u   = tid + i * 256;        // 2048 units: 128 rows x 16 units
        int row = u >> 4;
        int cu  = u & 15;
        cp_async16(base + AT_OFF + (uint32_t)(row * OROW + cu * 16),
                   Act + ((size_t)b * TT + row) * TT + cu * 8);
    }
    asm volatile("cp.async.commit_group;" ::: "memory");
    load_chunk(1, base + STAGE_B);
    asm volatile("cp.async.commit_group;" ::: "memory");

    float acc[4][4][4];
    #pragma unroll
    for (int i = 0; i < 4; i++)
        #pragma unroll
        for (int j = 0; j < 4; j++)
            #pragma unroll
            for (int r = 0; r < 4; r++) acc[i][j][r] = 0.f;

    const int sub = lane >> 3;
    const int lr  = lane & 7;
    const int a_row_off = (sub & 1) * 8 + lr;
    const int a_cu_off  = (sub >> 1);
    const int b_row_off = (sub >> 1) * 8 + lr;   // phase-1 non-trans B
    const int b_cu_off  = (sub & 1);
    const int bt_row_off = (sub & 1) * 8 + lr;   // phase-2 TRANS B (fixed!)
    const int bt_cu_off  = (sub >> 1);

    for (int c = 0; c < NCHUNK; c++) {
        const uint32_t st = base + (uint32_t)(c & 1) * STAGE_B;
        if (c < NCHUNK - 1) asm volatile("cp.async.wait_group 1;" ::: "memory");
        else                asm volatile("cp.async.wait_group 0;" ::: "memory");
        __syncthreads();

        #pragma unroll
        for (int ks = 0; ks < 2; ks++) {
            uint32_t aF[4][4], bF[4][2];
            #pragma unroll
            for (int mt = 0; mt < 4; mt++) {
                uint32_t off = SWZ((uint32_t)((wm + mt*16 + a_row_off) * 64
                                              + (ks*2 + a_cu_off) * 16));
                ldm_x4(aF[mt][0], aF[mt][1], aF[mt][2], aF[mt][3], st + ST_A + off);
            }
            #pragma unroll
            for (int np = 0; np < 2; np++) {
                uint32_t off = SWZ((uint32_t)((wn + np*16 + b_row_off) * 64
                                              + (ks*2 + b_cu_off) * 16));
                ldm_x4(bF[2*np][0], bF[2*np][1], bF[2*np+1][0], bF[2*np+1][1],
                       st + ST_B + off);
            }
            #pragma unroll
            for (int mt = 0; mt < 4; mt++)
                #pragma unroll
                for (int nt = 0; nt < 4; nt++)
                    mma16816h(acc[mt][nt], aF[mt], bF[nt]);
        }
        __syncthreads();
        if (c + 2 < NCHUNK) {
            load_chunk(c + 2, st);
            asm volatile("cp.async.commit_group;" ::: "memory");
        }
    }

    // ---- phase 1 epilogue: gtile (+bias) -> fp16 smem [s][n'] 272B rows ----
    const int q  = lane >> 2;
    const int i2 = (lane & 3) * 2;
    char* smem_gen = smem_raw + (base - smem_u32(smem_raw));
    #pragma unroll
    for (int mt = 0; mt < 4; mt++) {
        #pragma unroll
        for (int nt = 0; nt < 4; nt++) {
            int s0 = wm + mt*16 + q;          // local g row (= k of out)
            int n0 = wn + nt*8 + i2;          // local col
            float2 bv = *(const float2*)(bias + bn + n0);
            __half2 o0 = __half2(__float2half_rn(acc[mt][nt][0] + bv.x),
                                 __float2half_rn(acc[mt][nt][1] + bv.y));
            __half2 o1 = __half2(__float2half_rn(acc[mt][nt][2] + bv.x),
                                 __float2half_rn(acc[mt][nt][3] + bv.y));
            *(__half2*)(smem_gen + GT_OFF + s0 * OROW + n0 * 2)       = o0;
            *(__half2*)(smem_gen + GT_OFF + (s0 + 8) * OROW + n0 * 2) = o1;
        }
    }
    __syncthreads();

    // ---- phase 2: out tile = act[b] (at) @ gtile (gt), K = 128 ----
    #pragma unroll
    for (int i = 0; i < 4; i++)
        #pragma unroll
        for (int j = 0; j < 4; j++)
            #pragma unroll
            for (int r = 0; r < 4; r++) acc[i][j][r] = 0.f;

    #pragma unroll
    for (int ks = 0; ks < 8; ks++) {
        uint32_t aF[4][4], bF[4][2];
        #pragma unroll
        for (int mt = 0; mt < 4; mt++) {
            uint32_t off = (uint32_t)((wm + mt*16 + a_row_off) * OROW
                                      + ks*32 + a_cu_off * 16);
            ldm_x4(aF[mt][0], aF[mt][1], aF[mt][2], aF[mt][3], base + AT_OFF + off);
        }
        #pragma unroll
        for (int np = 0; np < 2; np++) {
            int n0 = wn + np*16;
            uint32_t off = (uint32_t)((ks*16 + bt_row_off) * OROW
                                      + n0*2 + bt_cu_off * 16);
            ldm_x4_t(bF[2*np][0], bF[2*np][1], bF[2*np+1][0], bF[2*np+1][1],
                     base + GT_OFF + off);
        }
        #pragma unroll
        for (int mt = 0; mt < 4; mt++)
            #pragma unroll
            for (int nt = 0; nt < 4; nt++)
                mma16816h(acc[mt][nt], aF[mt], bF[nt]);
    }

    #pragma unroll
    for (int mt = 0; mt < 4; mt++) {
        #pragma unroll
        for (int nt = 0; nt < 4; nt++) {
            int t0 = wm + mt*16 + q;
            int n0 = bn + wn + nt*8 + i2;
            float2 o0 = { acc[mt][nt][0], acc[mt][nt][1] };
            float2 o1 = { acc[mt][nt][2], acc[mt][nt][3] };
            *(float2*)(Out + ((size_t)b*TT + t0) * GOUT + n0)     = o0;
            *(float2*)(Out + ((size_t)b*TT + t0 + 8) * GOUT + n0) = o1;
        }
    }
}

// ---------------- q/k GEMM: 64x64 tile, split-bf16 mma (3-term) --------------
#define QK_BK 64
#define QK_NCH (CIN / QK_BK)
#define QK_AH 0
#define QK_AL 8192
#define QK_BH 16384
#define QK_BL 24576
#define QK_STAGE 32768
#define SMEM_QK (1024 + 2 * QK_STAGE)

__global__ void __launch_bounds__(128, 1)
qk_gemm_mma(const __nv_bfloat16* __restrict__ X1h, const __nv_bfloat16* __restrict__ X1l,
            const __nv_bfloat16* __restrict__ X2h, const __nv_bfloat16* __restrict__ X2l,
            const __nv_bfloat16* __restrict__ W1h, const __nv_bfloat16* __restrict__ W1l,
            const __nv_bfloat16* __restrict__ W2h, const __nv_bfloat16* __restrict__ W2l,
            const float* __restrict__ b1, const float* __restrict__ b2,
            float* __restrict__ Q, float* __restrict__ K)
{
    extern __shared__ char smem_raw[];
    const uint32_t base = (smem_u32(smem_raw) + 1023u) & ~1023u;

    const int sel = blockIdx.y;
    const __nv_bfloat16* Ah = sel ? X2h : X1h;
    const __nv_bfloat16* Al = sel ? X2l : X1l;
    const __nv_bfloat16* Bh = sel ? W2h : W1h;
    const __nv_bfloat16* Bl = sel ? W2l : W1l;
    const float* bias = sel ? b2 : b1;
    float* C = sel ? K : Q;

    const int tid  = threadIdx.x;
    const int wid  = tid >> 5;
    const int lane = tid & 31;
    const int bm = blockIdx.x * 64;
    const int wm = (wid >> 1) * 32;
    const int wn = (wid & 1) * 32;

    auto load_chunk = [&](int c, uint32_t st) {
        const int k0 = c * QK_BK;
        #pragma unroll
        for (int i = 0; i < 4; i++) {
            int u   = tid + i * 128;
            int row = u >> 3;
            int ku  = u & 7;
            uint32_t so = SWZ((uint32_t)(row * 128 + ku * 16));
            size_t ga = (size_t)(bm + row) * CIN + k0 + ku * 8;
            size_t gb = (size_t)row * CIN + k0 + ku * 8;
            cp_async16(st + QK_AH + so, Ah + ga);
            cp_async16(st + QK_AL + so, Al + ga);
            cp_async16(st + QK_BH + so, Bh + gb);
            cp_async16(st + QK_BL + so, Bl + gb);
        }
        asm volatile("cp.async.commit_group;" ::: "memory");
    };

    load_chunk(0, base);
    load_chunk(1, base + QK_STAGE);

    float acc[2][4][4];
    #pragma unroll
    for (int i = 0; i < 2; i++)
        #pragma unroll
        for (int j = 0; j < 4; j++)
            #pragma unroll
            for (int r = 0; r < 4; r++) acc[i][j][r] = 0.f;

    const int sub = lane >> 3;
    const int lr  = lane & 7;
    const int a_row_off = (sub & 1) * 8 + lr;
    const int a_cu_off  = (sub >> 1);
    const int b_row_off = (sub >> 1) * 8 + lr;
    const int b_cu_off  = (sub & 1);

    for (int c = 0; c < QK_NCH; c++) {
        const uint32_t st = base + (uint32_t)(c & 1) * QK_STAGE;
        if (c < QK_NCH - 1) asm volatile("cp.async.wait_group 1;" ::: "memory");
        else                asm volatile("cp.async.wait_group 0;" ::: "memory");
        __syncthreads();

        #pragma unroll
        for (int ks = 0; ks < 4; ks++) {
            uint32_t aH[2][4], aL[2][4], bH[4][2], bL[4][2];
            #pragma unroll
            for (int mt = 0; mt < 2; mt++) {
                uint32_t off = SWZ((uint32_t)((wm + mt*16 + a_row_off) * 128
                                              + (ks*2 + a_cu_off) * 16));
                ldm_x4(aH[mt][0], aH[mt][1], aH[mt][2], aH[mt][3], st + QK_AH + off);
                ldm_x4(aL[mt][0], aL[mt][1], aL[mt][2], aL[mt][3], st + QK_AL + off);
            }
            #pragma unroll
            for (int np = 0; np < 2; np++) {
                uint32_t off = SWZ((uint32_t)((wn + np*16 + b_row_off) * 128
                                              + (ks*2 + b_cu_off) * 16));
                ldm_x4(bH[2*np][0], bH[2*np][1], bH[2*np+1][0], bH[2*np+1][1],
                       st + QK_BH + off);
                ldm_x4(bL[2*np][0], bL[2*np][1], bL[2*np+1][0], bL[2*np+1][1],
                       st + QK_BL + off);
            }
            #pragma unroll
            for (int mt = 0; mt < 2; mt++)
                #pragma unroll
                for (int nt = 0; nt < 4; nt++)
                    mma16816(acc[mt][nt], aH[mt], bH[nt]);
            #pragma unroll
            for (int mt = 0; mt < 2; mt++)
                #pragma unroll
                for (int nt = 0; nt < 4; nt++)
                    mma16816(acc[mt][nt], aH[mt], bL[nt]);
            #pragma unroll
            for (int mt = 0; mt < 2; mt++)
                #pragma unroll
                for (int nt = 0; nt < 4; nt++)
                    mma16816(acc[mt][nt], aL[mt], bH[nt]);
        }
        __syncthreads();
        if (c + 2 < QK_NCH) load_chunk(c + 2, st);
    }

    const int q = lane >> 2;
    const int i2 = (lane & 3) * 2;
    #pragma unroll
    for (int mt = 0; mt < 2; mt++) {
        #pragma unroll
        for (int nt = 0; nt < 4; nt++) {
            int m0 = bm + wm + mt*16 + q;
            int n0 = wn + nt*8 + i2;
            float2 bv = *(const float2*)(bias + n0);
            float2 o0 = { acc[mt][nt][0] + bv.x, acc[mt][nt][1] + bv.y };
            float2 o1 = { acc[mt][nt][2] + bv.x, acc[mt][nt][3] + bv.y };
            *(float2*)(C + (size_t)m0 * NF + n0)     = o0;
            *(float2*)(C + (size_t)(m0+8) * NF + n0) = o1;
        }
    }
}

// ---------------- scores + fused activation -> act fp16 ----------------------
__global__ void __launch_bounds__(512)
scores_act_kernel(const float* __restrict__ actw,
                  const float* __restrict__ qb,
                  const float* __restrict__ kb,
                  __half* __restrict__ af)
{
    const int b  = blockIdx.x;
    const int s  = blockIdx.y * 32 + (threadIdx.x >> 4);
    const int tp = threadIdx.x & 15;

    __shared__ float qs[TT * NF];
    for (int idx = threadIdx.x; idx < TT*NF; idx += 512)
        qs[idx] = qb[(size_t)b*TT*NF + idx];

    float kr[NF];
    #pragma unroll
    for (int f = 0; f < NF; ++f) kr[f] = kb[((size_t)b*TT + s)*NF + f];
    __syncthreads();

    float col[8];
    float mx = -1e30f;
    #pragma unroll
    for (int i = 0; i < 8; ++i) {
        const float* qrow = qs + (tp*8 + i)*NF;
        float v = 0.f;
        #pragma unroll
        for (int f = 0; f < NF; ++f) v = fmaf(qrow[f], kr[f], v);
        col[i] = v;
        mx = fmaxf(mx, v);
    }
    #pragma unroll
    for (int d = 1; d < 16; d <<= 1)
        mx = fmaxf(mx, __shfl_xor_sync(0xffffffffu, mx, d));
    float sum = 0.f;
    #pragma unroll
    for (int i = 0; i < 8; ++i) sum += expf(col[i] - mx);
    #pragma unroll
    for (int d = 1; d < 16; d <<= 1)
        sum += __shfl_xor_sync(0xffffffffu, sum, d);
    const float inv = 1.f / sum;
    const float w0 = actw[0], w1 = actw[1], w2 = actw[2];
    __half* pf = af + (size_t)b*TT*TT + s;
    #pragma unroll
    for (int i = 0; i < 8; ++i) {
        int t = tp*8 + i;
        float v = col[i];
        float a = w0 * fmaxf(v, 0.f)
                + w1 * (1.f / (1.f + expf(-v)))
                + w2 * (expf(v - mx) * inv);
        pf[t*TT] = __float2half_rn(a);
    }
}

// ---------------------------------------------------------------------------
extern "C" void kernel_launch(void* const* d_in, const int* in_sizes, int n_in,
                              void* d_out, int out_size)
{
    const float* x1   = (const float*)d_in[0];
    const float* x2   = (const float*)d_in[1];
    const float* actw = (const float*)d_in[2];
    const float* w1   = (const float*)d_in[3];
    const float* b1   = (const float*)d_in[4];
    const float* w2   = (const float*)d_in[5];
    const float* b2   = (const float*)d_in[6];
    const float* wg   = (const float*)d_in[7];
    const float* bg   = (const float*)d_in[8];
    float* out = (float*)d_out;

    float *qp, *kp;
    __nv_bfloat16 *ahp, *alp, *x2hp, *x2lp;
    __nv_bfloat16 *w1hp, *w1lp, *w2hp, *w2lp;
    __half *x1fp, *wgfp, *actfp;
    cudaGetSymbolAddress((void**)&qp, q_buf);
    cudaGetSymbolAddress((void**)&kp, k_buf);
    cudaGetSymbolAddress((void**)&ahp, a_hi);
    cudaGetSymbolAddress((void**)&alp, a_lo);
    cudaGetSymbolAddress((void**)&x2hp, x2h);
    cudaGetSymbolAddress((void**)&x2lp, x2l);
    cudaGetSymbolAddress((void**)&x1fp, x1f);
    cudaGetSymbolAddress((void**)&wgfp, wgf);
    cudaGetSymbolAddress((void**)&actfp, act_f);
    cudaGetSymbolAddress((void**)&w1hp, w1h);
    cudaGetSymbolAddress((void**)&w1lp, w1l);
    cudaGetSymbolAddress((void**)&w2hp, w2h);
    cudaGetSymbolAddress((void**)&w2lp, w2l);

    cudaFuncSetAttribute(g_out_gemm, cudaFuncAttributeMaxDynamicSharedMemorySize, SMEM_G);
    cudaFuncSetAttribute(qk_gemm_mma, cudaFuncAttributeMaxDynamicSharedMemorySize, SMEM_QK);

    // conversions
    {
        int n4 = (BT * CIN) / 4;
        conv_x1   <<<(n4 + 255) / 256, 256>>>(x1, ahp, alp, x1fp, n4);
        split_bf16<<<(n4 + 255) / 256, 256>>>(x2, x2hp, x2lp, n4);
        conv_f16  <<<(n4 + 255) / 256, 256>>>(wg, wgfp, n4);
        int w4 = (NF * CIN) / 4;
        split_bf16<<<(w4 + 255) / 256, 256>>>(w1, w1hp, w1lp, w4);
        split_bf16<<<(w4 + 255) / 256, 256>>>(w2, w2hp, w2lp, w4);
    }

    // q and k projections (bf16 3-term — protects softmax inputs)
    qk_gemm_mma<<<dim3(BT/64, 2), 128, SMEM_QK>>>(ahp, alp, x2hp, x2lp,
                                                  w1hp, w1lp, w2hp, w2lp,
                                                  b1, b2, qp, kp);

    // scores -> fused activation -> act fp16 (must precede fused g+out)
    scores_act_kernel<<<dim3(NB, 4), 512>>>(actw, qp, kp, actfp);

    // fused: g tile (fp16 1-term) -> epilogue out tile = act[b] @ gtile
    g_out_gemm<<<dim3(GOUT/128, NB), 256, SMEM_G>>>(x1fp, wgfp, bg, actfp, out);
}

// round 11
// speedup vs baseline: 2.4178x; 1.0593x over previous
#include <cuda_runtime.h>
#include <cuda_fp16.h>
#include <math.h>
#include <stdint.h>

#define NB   32
#define TT   128
#define BT   4096
#define CIN  4096
#define NF   64
#define GOUT 4096

// ---------------- scratch (device globals; no allocation allowed) ----------
__device__ float q_buf[(size_t)NB * TT * NF];
__device__ float k_buf[(size_t)NB * TT * NF];
__device__ __align__(1024) __half x1f[(size_t)BT * CIN];       // x1 fp16 (qk A, g A)
__device__ __align__(1024) __half x2f[(size_t)BT * CIN];       // x2 fp16 (k A)
__device__ __align__(1024) __half wgf[(size_t)GOUT * CIN];     // wg fp16 (g B)
__device__ __align__(1024) __half w1f[(size_t)NF * CIN];       // w1 fp16
__device__ __align__(1024) __half w2f[(size_t)NF * CIN];       // w2 fp16
__device__ __align__(1024) __half act_f[(size_t)NB * TT * TT]; // act fp16

// ---------------- small PTX helpers ----------------------------------------
__device__ __forceinline__ uint32_t smem_u32(const void* p) {
    uint32_t a;
    asm("{ .reg .u64 t; cvta.to.shared.u64 t, %1; cvt.u32.u64 %0, t; }" : "=r"(a) : "l"(p));
    return a;
}
__device__ __forceinline__ void cp_async16(uint32_t dst, const void* src) {
    asm volatile("cp.async.cg.shared.global [%0], [%1], 16;" :: "r"(dst), "l"(src) : "memory");
}
__device__ __forceinline__ void ldm_x4(uint32_t& r0, uint32_t& r1, uint32_t& r2, uint32_t& r3,
                                       uint32_t addr) {
    asm volatile("ldmatrix.sync.aligned.m8n8.x4.shared.b16 {%0,%1,%2,%3}, [%4];"
                 : "=r"(r0), "=r"(r1), "=r"(r2), "=r"(r3) : "r"(addr));
}
__device__ __forceinline__ void ldm_x4_t(uint32_t& r0, uint32_t& r1, uint32_t& r2, uint32_t& r3,
                                         uint32_t addr) {
    asm volatile("ldmatrix.sync.aligned.m8n8.x4.trans.shared.b16 {%0,%1,%2,%3}, [%4];"
                 : "=r"(r0), "=r"(r1), "=r"(r2), "=r"(r3) : "r"(addr));
}
__device__ __forceinline__ void mma16816h(float* c, const uint32_t* a, const uint32_t* b) {
    asm volatile("mma.sync.aligned.m16n8k16.row.col.f32.f16.f16.f32 "
                 "{%0,%1,%2,%3}, {%4,%5,%6,%7}, {%8,%9}, {%0,%1,%2,%3};"
                 : "+f"(c[0]), "+f"(c[1]), "+f"(c[2]), "+f"(c[3])
                 : "r"(a[0]), "r"(a[1]), "r"(a[2]), "r"(a[3]), "r"(b[0]), "r"(b[1]));
}
#define SWZ(o) ((o) ^ (((o) >> 3) & 0x70))

// ---------------- conversion kernel ------------------------------------------
__global__ void __launch_bounds__(256)
conv_f16(const float* __restrict__ x, __half* __restrict__ h, int n4)
{
    int i = blockIdx.x * blockDim.x + threadIdx.x;
    if (i >= n4) return;
    float4 v = ((const float4*)x)[i];
    ((__half2*)h)[2*i]   = __half2(__float2half_rn(v.x), __float2half_rn(v.y));
    ((__half2*)h)[2*i+1] = __half2(__float2half_rn(v.z), __float2half_rn(v.w));
}

// ---------------- fused g + out GEMM ------------------------------------------
// Phase 1: gtile = fp16(x1[b-block]) @ fp16(wg[bn-block])^T + bg  (K=4096)
// Phase 2: out[b][:, bn:bn+128] = act[b] @ gtile                  (K=128)
#define BKC 32
#define NCHUNK (CIN / BKC)
#define ST_A  0
#define ST_B  8192
#define STAGE_B 16384
#define OROW 272
#define GT_OFF 32768
#define AT_OFF (32768 + 128 * OROW)
#define SMEM_G (1024 + 32768 + 2 * 128 * OROW)

__global__ void __launch_bounds__(256, 2)
g_out_gemm(const __half* __restrict__ A, const __half* __restrict__ B,
           const float* __restrict__ bias, const __half* __restrict__ Act,
           float* __restrict__ Out)
{
    extern __shared__ char smem_raw[];
    const uint32_t base = (smem_u32(smem_raw) + 1023u) & ~1023u;

    const int tid  = threadIdx.x;
    const int wid  = tid >> 5;
    const int lane = tid & 31;
    const int b  = blockIdx.y;          // batch = row-block of g
    const int bm = b * 128;
    const int bn = blockIdx.x * 128;
    const int wm = (wid >> 2) * 64;
    const int wn = (wid & 3) * 32;

    auto load_chunk = [&](int c, uint32_t st) {
        const int k0 = c * BKC;
        #pragma unroll
        for (int i = 0; i < 2; i++) {
            int u   = tid + i * 256;
            int row = u >> 2;
            int cu  = u & 3;
            uint32_t so = SWZ((uint32_t)(row * 64 + cu * 16));
            cp_async16(st + ST_A + so, A + (size_t)(bm + row) * CIN + k0 + cu * 8);
            cp_async16(st + ST_B + so, B + (size_t)(bn + row) * CIN + k0 + cu * 8);
        }
    };

    // chunk 0 + act[b] share the first commit group (scores ran earlier)
    load_chunk(0, base);
    #pragma unroll
    for (int i = 0; i < 8; i++) {
        int u   = tid + i * 256;
        int row = u >> 4;
        int cu  = u & 15;
        cp_async16(base + AT_OFF + (uint32_t)(row * OROW + cu * 16),
                   Act + ((size_t)b * TT + row) * TT + cu * 8);
    }
    asm volatile("cp.async.commit_group;" ::: "memory");
    load_chunk(1, base + STAGE_B);
    asm volatile("cp.async.commit_group;" ::: "memory");

    float acc[4][4][4];
    #pragma unroll
    for (int i = 0; i < 4; i++)
        #pragma unroll
        for (int j = 0; j < 4; j++)
            #pragma unroll
            for (int r = 0; r < 4; r++) acc[i][j][r] = 0.f;

    const int sub = lane >> 3;
    const int lr  = lane & 7;
    const int a_row_off = (sub & 1) * 8 + lr;
    const int a_cu_off  = (sub >> 1);
    const int b_row_off = (sub >> 1) * 8 + lr;   // phase-1 non-trans B
    const int b_cu_off  = (sub & 1);
    const int bt_row_off = (sub & 1) * 8 + lr;   // phase-2 trans B
    const int bt_cu_off  = (sub >> 1);

    for (int c = 0; c < NCHUNK; c++) {
        const uint32_t st = base + (uint32_t)(c & 1) * STAGE_B;
        if (c < NCHUNK - 1) asm volatile("cp.async.wait_group 1;" ::: "memory");
        else                asm volatile("cp.async.wait_group 0;" ::: "memory");
        __syncthreads();

        #pragma unroll
        for (int ks = 0; ks < 2; ks++) {
            uint32_t aF[4][4], bF[4][2];
            #pragma unroll
            for (int mt = 0; mt < 4; mt++) {
                uint32_t off = SWZ((uint32_t)((wm + mt*16 + a_row_off) * 64
                                              + (ks*2 + a_cu_off) * 16));
                ldm_x4(aF[mt][0], aF[mt][1], aF[mt][2], aF[mt][3], st + ST_A + off);
            }
            #pragma unroll
            for (int np = 0; np < 2; np++) {
                uint32_t off = SWZ((uint32_t)((wn + np*16 + b_row_off) * 64
                                              + (ks*2 + b_cu_off) * 16));
                ldm_x4(bF[2*np][0], bF[2*np][1], bF[2*np+1][0], bF[2*np+1][1],
                       st + ST_B + off);
            }
            #pragma unroll
            for (int mt = 0; mt < 4; mt++)
                #pragma unroll
                for (int nt = 0; nt < 4; nt++)
                    mma16816h(acc[mt][nt], aF[mt], bF[nt]);
        }
        __syncthreads();
        if (c + 2 < NCHUNK) {
            load_chunk(c + 2, st);
            asm volatile("cp.async.commit_group;" ::: "memory");
        }
    }

    // ---- phase 1 epilogue: gtile (+bias) -> fp16 smem [s][n'] 272B rows ----
    const int q  = lane >> 2;
    const int i2 = (lane & 3) * 2;
    char* smem_gen = smem_raw + (base - smem_u32(smem_raw));
    #pragma unroll
    for (int mt = 0; mt < 4; mt++) {
        #pragma unroll
        for (int nt = 0; nt < 4; nt++) {
            int s0 = wm + mt*16 + q;
            int n0 = wn + nt*8 + i2;
            float2 bv = *(const float2*)(bias + bn + n0);
            __half2 o0 = __half2(__float2half_rn(acc[mt][nt][0] + bv.x),
                                 __float2half_rn(acc[mt][nt][1] + bv.y));
            __half2 o1 = __half2(__float2half_rn(acc[mt][nt][2] + bv.x),
                                 __float2half_rn(acc[mt][nt][3] + bv.y));
            *(__half2*)(smem_gen + GT_OFF + s0 * OROW + n0 * 2)       = o0;
            *(__half2*)(smem_gen + GT_OFF + (s0 + 8) * OROW + n0 * 2) = o1;
        }
    }
    __syncthreads();

    // ---- phase 2: out tile = act[b] @ gtile, K = 128 ----
    #pragma unroll
    for (int i = 0; i < 4; i++)
        #pragma unroll
        for (int j = 0; j < 4; j++)
            #pragma unroll
            for (int r = 0; r < 4; r++) acc[i][j][r] = 0.f;

    #pragma unroll
    for (int ks = 0; ks < 8; ks++) {
        uint32_t aF[4][4], bF[4][2];
        #pragma unroll
        for (int mt = 0; mt < 4; mt++) {
            uint32_t off = (uint32_t)((wm + mt*16 + a_row_off) * OROW
                                      + ks*32 + a_cu_off * 16);
            ldm_x4(aF[mt][0], aF[mt][1], aF[mt][2], aF[mt][3], base + AT_OFF + off);
        }
        #pragma unroll
        for (int np = 0; np < 2; np++) {
            int n0 = wn + np*16;
            uint32_t off = (uint32_t)((ks*16 + bt_row_off) * OROW
                                      + n0*2 + bt_cu_off * 16);
            ldm_x4_t(bF[2*np][0], bF[2*np][1], bF[2*np+1][0], bF[2*np+1][1],
                     base + GT_OFF + off);
        }
        #pragma unroll
        for (int mt = 0; mt < 4; mt++)
            #pragma unroll
            for (int nt = 0; nt < 4; nt++)
                mma16816h(acc[mt][nt], aF[mt], bF[nt]);
    }

    #pragma unroll
    for (int mt = 0; mt < 4; mt++) {
        #pragma unroll
        for (int nt = 0; nt < 4; nt++) {
            int t0 = wm + mt*16 + q;
            int n0 = bn + wn + nt*8 + i2;
            float2 o0 = { acc[mt][nt][0], acc[mt][nt][1] };
            float2 o1 = { acc[mt][nt][2], acc[mt][nt][3] };
            *(float2*)(Out + ((size_t)b*TT + t0) * GOUT + n0)     = o0;
            *(float2*)(Out + ((size_t)b*TT + t0 + 8) * GOUT + n0) = o1;
        }
    }
}

// ---------------- q/k GEMM: 64x64 tile, pure fp16 1-term ---------------------
// grid (BT/64, 2): y==0 -> q = x1@w1^T+b1 ; y==1 -> k = x2@w2^T+b2
#define QK_BK 64
#define QK_NCH (CIN / QK_BK)
#define QK_A 0
#define QK_B 8192
#define QK_STAGE 16384
#define SMEM_QK (1024 + 2 * QK_STAGE)

__global__ void __launch_bounds__(128, 1)
qk_gemm_f16(const __half* __restrict__ X1, const __half* __restrict__ X2,
            const __half* __restrict__ W1, const __half* __restrict__ W2,
            const float* __restrict__ b1, const float* __restrict__ b2,
            float* __restrict__ Q, float* __restrict__ K)
{
    extern __shared__ char smem_raw[];
    const uint32_t base = (smem_u32(smem_raw) + 1023u) & ~1023u;

    const int sel = blockIdx.y;
    const __half* A = sel ? X2 : X1;
    const __half* B = sel ? W2 : W1;
    const float* bias = sel ? b2 : b1;
    float* C = sel ? K : Q;

    const int tid  = threadIdx.x;
    const int wid  = tid >> 5;
    const int lane = tid & 31;
    const int bm = blockIdx.x * 64;
    const int wm = (wid >> 1) * 32;
    const int wn = (wid & 1) * 32;

    auto load_chunk = [&](int c, uint32_t st) {
        const int k0 = c * QK_BK;
        #pragma unroll
        for (int i = 0; i < 4; i++) {
            int u   = tid + i * 128;     // 512 16B-units per tile
            int row = u >> 3;
            int ku  = u & 7;
            uint32_t so = SWZ((uint32_t)(row * 128 + ku * 16));
            cp_async16(st + QK_A + so, A + (size_t)(bm + row) * CIN + k0 + ku * 8);
            cp_async16(st + QK_B + so, B + (size_t)row * CIN + k0 + ku * 8);
        }
        asm volatile("cp.async.commit_group;" ::: "memory");
    };

    load_chunk(0, base);
    load_chunk(1, base + QK_STAGE);

    float acc[2][4][4];
    #pragma unroll
    for (int i = 0; i < 2; i++)
        #pragma unroll
        for (int j = 0; j < 4; j++)
            #pragma unroll
            for (int r = 0; r < 4; r++) acc[i][j][r] = 0.f;

    const int sub = lane >> 3;
    const int lr  = lane & 7;
    const int a_row_off = (sub & 1) * 8 + lr;
    const int a_cu_off  = (sub >> 1);
    const int b_row_off = (sub >> 1) * 8 + lr;
    const int b_cu_off  = (sub & 1);

    for (int c = 0; c < QK_NCH; c++) {
        const uint32_t st = base + (uint32_t)(c & 1) * QK_STAGE;
        if (c < QK_NCH - 1) asm volatile("cp.async.wait_group 1;" ::: "memory");
        else                asm volatile("cp.async.wait_group 0;" ::: "memory");
        __syncthreads();

        #pragma unroll
        for (int ks = 0; ks < 4; ks++) {
            uint32_t aF[2][4], bF[4][2];
            #pragma unroll
            for (int mt = 0; mt < 2; mt++) {
                uint32_t off = SWZ((uint32_t)((wm + mt*16 + a_row_off) * 128
                                              + (ks*2 + a_cu_off) * 16));
                ldm_x4(aF[mt][0], aF[mt][1], aF[mt][2], aF[mt][3], st + QK_A + off);
            }
            #pragma unroll
            for (int np = 0; np < 2; np++) {
                uint32_t off = SWZ((uint32_t)((wn + np*16 + b_row_off) * 128
                                              + (ks*2 + b_cu_off) * 16));
                ldm_x4(bF[2*np][0], bF[2*np][1], bF[2*np+1][0], bF[2*np+1][1],
                       st + QK_B + off);
            }
            #pragma unroll
            for (int mt = 0; mt < 2; mt++)
                #pragma unroll
                for (int nt = 0; nt < 4; nt++)
                    mma16816h(acc[mt][nt], aF[mt], bF[nt]);
        }
        __syncthreads();
        if (c + 2 < QK_NCH) load_chunk(c + 2, st);
    }

    const int q = lane >> 2;
    const int i2 = (lane & 3) * 2;
    #pragma unroll
    for (int mt = 0; mt < 2; mt++) {
        #pragma unroll
        for (int nt = 0; nt < 4; nt++) {
            int m0 = bm + wm + mt*16 + q;
            int n0 = wn + nt*8 + i2;
            float2 bv = *(const float2*)(bias + n0);
            float2 o0 = { acc[mt][nt][0] + bv.x, acc[mt][nt][1] + bv.y };
            float2 o1 = { acc[mt][nt][2] + bv.x, acc[mt][nt][3] + bv.y };
            *(float2*)(C + (size_t)m0 * NF + n0)     = o0;
            *(float2*)(C + (size_t)(m0+8) * NF + n0) = o1;
        }
    }
}

// ---------------- scores + fused activation -> act fp16 ----------------------
__global__ void __launch_bounds__(512)
scores_act_kernel(const float* __restrict__ actw,
                  const float* __restrict__ qb,
                  const float* __restrict__ kb,
                  __half* __restrict__ af)
{
    const int b  = blockIdx.x;
    const int s  = blockIdx.y * 32 + (threadIdx.x >> 4);
    const int tp = threadIdx.x & 15;

    __shared__ float qs[TT * NF];
    for (int idx = threadIdx.x; idx < TT*NF; idx += 512)
        qs[idx] = qb[(size_t)b*TT*NF + idx];

    float kr[NF];
    #pragma unroll
    for (int f = 0; f < NF; ++f) kr[f] = kb[((size_t)b*TT + s)*NF + f];
    __syncthreads();

    float col[8];
    float mx = -1e30f;
    #pragma unroll
    for (int i = 0; i < 8; ++i) {
        const float* qrow = qs + (tp*8 + i)*NF;
        float v = 0.f;
        #pragma unroll
        for (int f = 0; f < NF; ++f) v = fmaf(qrow[f], kr[f], v);
        col[i] = v;
        mx = fmaxf(mx, v);
    }
    #pragma unroll
    for (int d = 1; d < 16; d <<= 1)
        mx = fmaxf(mx, __shfl_xor_sync(0xffffffffu, mx, d));
    float sum = 0.f;
    #pragma unroll
    for (int i = 0; i < 8; ++i) sum += expf(col[i] - mx);
    #pragma unroll
    for (int d = 1; d < 16; d <<= 1)
        sum += __shfl_xor_sync(0xffffffffu, sum, d);
    const float inv = 1.f / sum;
    const float w0 = actw[0], w1 = actw[1], w2 = actw[2];
    __half* pf = af + (size_t)b*TT*TT + s;
    #pragma unroll
    for (int i = 0; i < 8; ++i) {
        int t = tp*8 + i;
        float v = col[i];
        float a = w0 * fmaxf(v, 0.f)
                + w1 * (1.f / (1.f + expf(-v)))
                + w2 * (expf(v - mx) * inv);
        pf[t*TT] = __float2half_rn(a);
    }
}

// ---------------------------------------------------------------------------
extern "C" void kernel_launch(void* const* d_in, const int* in_sizes, int n_in,
                              void* d_out, int out_size)
{
    const float* x1   = (const float*)d_in[0];
    const float* x2   = (const float*)d_in[1];
    const float* actw = (const float*)d_in[2];
    const float* w1   = (const float*)d_in[3];
    const float* b1   = (const float*)d_in[4];
    const float* w2   = (const float*)d_in[5];
    const float* b2   = (const float*)d_in[6];
    const float* wg   = (const float*)d_in[7];
    const float* bg   = (const float*)d_in[8];
    float* out = (float*)d_out;

    float *qp, *kp;
    __half *x1fp, *x2fp, *wgfp, *w1fp, *w2fp, *actfp;
    cudaGetSymbolAddress((void**)&qp, q_buf);
    cudaGetSymbolAddress((void**)&kp, k_buf);
    cudaGetSymbolAddress((void**)&x1fp, x1f);
    cudaGetSymbolAddress((void**)&x2fp, x2f);
    cudaGetSymbolAddress((void**)&wgfp, wgf);
    cudaGetSymbolAddress((void**)&w1fp, w1f);
    cudaGetSymbolAddress((void**)&w2fp, w2f);
    cudaGetSymbolAddress((void**)&actfp, act_f);

    cudaFuncSetAttribute(g_out_gemm, cudaFuncAttributeMaxDynamicSharedMemorySize, SMEM_G);
    cudaFuncSetAttribute(qk_gemm_f16, cudaFuncAttributeMaxDynamicSharedMemorySize, SMEM_QK);

    // conversions (all fp16 single)
    {
        int n4 = (BT * CIN) / 4;
        conv_f16<<<(n4 + 255) / 256, 256>>>(x1, x1fp, n4);
        conv_f16<<<(n4 + 255) / 256, 256>>>(x2, x2fp, n4);
        conv_f16<<<(n4 + 255) / 256, 256>>>(wg, wgfp, n4);
        int w4 = (NF * CIN) / 4;
        conv_f16<<<(w4 + 255) / 256, 256>>>(w1, w1fp, w4);
        conv_f16<<<(w4 + 255) / 256, 256>>>(w2, w2fp, w4);
    }

    // q and k projections (pure fp16 1-term)
    qk_gemm_f16<<<dim3(BT/64, 2), 128, SMEM_QK>>>(x1fp, x2fp, w1fp, w2fp,
                                                  b1, b2, qp, kp);

    // scores -> fused activation -> act fp16 (must precede fused g+out)
    scores_act_kernel<<<dim3(NB, 4), 512>>>(actw, qp, kp, actfp);

    // fused: g tile (fp16 1-term) -> epilogue out tile = act[b] @ gtile
    g_out_gemm<<<dim3(GOUT/128, NB), 256, SMEM_G>>>(x1fp, wgfp, bg, actfp, out);
}